// round 1
// baseline (speedup 1.0000x reference)
#include <cuda_runtime.h>
#include <cstddef>

#define Bb   4
#define Ss   1024
#define Dd   1024
#define Hh   16
#define DKk  64
#define DFFf 4096
#define Mrows (Bb*Ss)

// ---------------- scratch (device globals; no allocation) ----------------
__device__ float g_q   [(size_t)Mrows*Dd];
__device__ float g_k   [(size_t)Mrows*Dd];
__device__ float g_v   [(size_t)Mrows*Dd];
__device__ float g_rq  [(size_t)Mrows*Dd];
__device__ float g_rk  [(size_t)Mrows*Dd];
__device__ float g_sc  [(size_t)Bb*Hh*Ss*Ss];   // scores, reused as softmax weights
__device__ float g_qc  [(size_t)Bb*Hh*Ss*Ss];   // quantum bias
__device__ float g_attn[(size_t)Mrows*Dd];
__device__ float g_tmp [(size_t)Mrows*Dd];
__device__ float g_x1  [(size_t)Mrows*Dd];
__device__ float g_hh  [(size_t)Mrows*DFFf];

// ---------------- reductions ----------------
__device__ __forceinline__ float warpSum(float v){
#pragma unroll
    for (int o=16;o;o>>=1) v += __shfl_xor_sync(0xffffffffu, v, o);
    return v;
}
__device__ __forceinline__ float warpMax(float v){
#pragma unroll
    for (int o=16;o;o>>=1) v = fmaxf(v, __shfl_xor_sync(0xffffffffu, v, o));
    return v;
}
// 256-thread block reductions (8 warps)
__device__ __forceinline__ float blockSum(float v, float* red){
    int lane = threadIdx.x & 31, w = threadIdx.x >> 5;
    v = warpSum(v);
    __syncthreads();
    if (lane == 0) red[w] = v;
    __syncthreads();
    float r = red[0];
#pragma unroll
    for (int i=1;i<8;i++) r += red[i];
    return r;
}
__device__ __forceinline__ float blockMax(float v, float* red){
    int lane = threadIdx.x & 31, w = threadIdx.x >> 5;
    v = warpMax(v);
    __syncthreads();
    if (lane == 0) red[w] = v;
    __syncthreads();
    float r = red[0];
#pragma unroll
    for (int i=1;i<8;i++) r = fmaxf(r, red[i]);
    return r;
}

// ---------------- generic SGEMM: C = A @ B(^T) + bias, epilogues ----------------
// BMODE 0: B operand is W[N,K] row-major (ldb = K)        -> B[k][n] = W[n*ldb + k]
// BMODE 1: B operand is matrix [K, N] row-major (ldb)     -> B[k][n] = B[k*ldb + n]
// EPI 0: none; 1: exact GELU * (1 + 0.1|sin 2*theta|); 2: cos(pi * sigmoid(x))
template<int BMODE, int EPI>
__global__ void __launch_bounds__(256) gemm_k(
    const float* __restrict__ A, const float* __restrict__ Bp,
    const float* __restrict__ bias, float* __restrict__ C,
    int M, int N, int K, int lda, int ldb, int ldc,
    long sA, long sB, long sB2, long sC, long sC2, int Hdim,
    const float* __restrict__ extra)
{
    const int BM=128, BN=64, BK=16;
    int z = blockIdx.z;
    const float* Az = A + (long)z * sA;
    long boff, coff;
    if (Hdim > 1) {
        int zb = z / Hdim, zh = z % Hdim;
        boff = (long)zb*sB + (long)zh*sB2;
        coff = (long)zb*sC + (long)zh*sC2;
    } else {
        boff = (long)z*sB;
        coff = (long)z*sC;
    }
    const float* Bz = Bp + boff;
    float* Cz = C + coff;

    int n0 = blockIdx.x * BN;
    int m0 = blockIdx.y * BM;
    int tid = threadIdx.x;
    int tx = tid & 15, ty = tid >> 4;

    __shared__ float As[BK][BM];
    __shared__ float Bs[BK][BN];

    float acc[8][4];
#pragma unroll
    for (int i=0;i<8;i++)
#pragma unroll
        for (int j=0;j<4;j++) acc[i][j] = 0.f;

    int am  = tid >> 2;        // 0..63
    int akq = (tid & 3) * 4;   // k sub-offset
    int bk_ = tid >> 4;        // BMODE1: 0..15 (k)
    int bnq = tid & 15;        // BMODE1: n/4

    for (int k0 = 0; k0 < K; k0 += BK) {
        // A tile (rows am, am+64), float4 along k, transposed store
        float4 a0 = *(const float4*)(Az + (size_t)(m0+am   )*lda + k0 + akq);
        float4 a1 = *(const float4*)(Az + (size_t)(m0+am+64)*lda + k0 + akq);
        As[akq+0][am] = a0.x; As[akq+1][am] = a0.y; As[akq+2][am] = a0.z; As[akq+3][am] = a0.w;
        As[akq+0][am+64] = a1.x; As[akq+1][am+64] = a1.y; As[akq+2][am+64] = a1.z; As[akq+3][am+64] = a1.w;
        if (BMODE == 0) {
            float4 w = *(const float4*)(Bz + (size_t)(n0+am)*ldb + k0 + akq);
            Bs[akq+0][am] = w.x; Bs[akq+1][am] = w.y; Bs[akq+2][am] = w.z; Bs[akq+3][am] = w.w;
        } else {
            float4 w = *(const float4*)(Bz + (size_t)(k0+bk_)*ldb + n0 + bnq*4);
            *(float4*)&Bs[bk_][bnq*4] = w;
        }
        __syncthreads();
#pragma unroll
        for (int kk=0; kk<BK; kk++){
            float4 aa = *(float4*)&As[kk][ty*8];
            float4 ab = *(float4*)&As[kk][ty*8+4];
            float4 bb = *(float4*)&Bs[kk][tx*4];
            float ar[8] = {aa.x,aa.y,aa.z,aa.w, ab.x,ab.y,ab.z,ab.w};
            float br[4] = {bb.x,bb.y,bb.z,bb.w};
#pragma unroll
            for (int i=0;i<8;i++)
#pragma unroll
                for (int j=0;j<4;j++) acc[i][j] = fmaf(ar[i], br[j], acc[i][j]);
        }
        __syncthreads();
    }

    float bias4[4];
#pragma unroll
    for (int j=0;j<4;j++) bias4[j] = bias ? bias[n0 + tx*4 + j] : 0.f;

#pragma unroll
    for (int i=0;i<8;i++){
        float vals[4];
#pragma unroll
        for (int j=0;j<4;j++){
            float v = acc[i][j] + bias4[j];
            if (EPI == 1){
                float ge = 0.5f * v * (1.f + erff(v * 0.70710678118654752f));
                float th = extra[n0 + tx*4 + j];
                v = ge * (1.f + 0.1f * fabsf(sinf(2.f*th)));
            } else if (EPI == 2){
                float s = 1.f / (1.f + expf(-v));
                v = cospif(s);   // cos(2*theta), theta = sigmoid*pi/2
            }
            vals[j] = v;
        }
        float4 o = make_float4(vals[0], vals[1], vals[2], vals[3]);
        *(float4*)(Cz + (size_t)(m0 + ty*8 + i)*ldc + n0 + tx*4) = o;
    }
}

// ---------------- fused scores + quantum-correlation kernel ----------------
// per (b,h): scores[i,j] = q_i . k_j / 8 ; qc[i,j] = rq_i . rk_j * strength[h]
// causal tile skip: whole tile masked iff j0 > i0+63
__global__ void __launch_bounds__(256) scores_k(
    const float* __restrict__ q, const float* __restrict__ kmat,
    const float* __restrict__ rq, const float* __restrict__ rk,
    const float* __restrict__ strengths,
    float* __restrict__ sc, float* __restrict__ qc)
{
    int bj = blockIdx.x, bi = blockIdx.y;
    if (bj > bi) return;                       // fully masked tile
    int z = blockIdx.z;
    int b = z >> 4, h = z & 15;
    int i0 = bi*64, j0 = bj*64;
    size_t base = (size_t)b*Ss*Dd + (size_t)h*DKk;

    __shared__ float Qs[16][64], Ks[16][64], RQs[16][64], RKs[16][64];
    int tid = threadIdx.x;
    int tx = tid & 15, ty = tid >> 4;
    int m  = tid >> 2;
    int kq = (tid & 3) * 4;

    float as[4][4], ac[4][4];
#pragma unroll
    for (int i=0;i<4;i++)
#pragma unroll
        for (int j=0;j<4;j++){ as[i][j]=0.f; ac[i][j]=0.f; }

    for (int k0=0; k0<64; k0+=16){
        float4 a = *(const float4*)(q    + base + (size_t)(i0+m)*Dd + k0 + kq);
        float4 c = *(const float4*)(rq   + base + (size_t)(i0+m)*Dd + k0 + kq);
        float4 d = *(const float4*)(kmat + base + (size_t)(j0+m)*Dd + k0 + kq);
        float4 e = *(const float4*)(rk   + base + (size_t)(j0+m)*Dd + k0 + kq);
        Qs [kq+0][m]=a.x; Qs [kq+1][m]=a.y; Qs [kq+2][m]=a.z; Qs [kq+3][m]=a.w;
        RQs[kq+0][m]=c.x; RQs[kq+1][m]=c.y; RQs[kq+2][m]=c.z; RQs[kq+3][m]=c.w;
        Ks [kq+0][m]=d.x; Ks [kq+1][m]=d.y; Ks [kq+2][m]=d.z; Ks [kq+3][m]=d.w;
        RKs[kq+0][m]=e.x; RKs[kq+1][m]=e.y; RKs[kq+2][m]=e.z; RKs[kq+3][m]=e.w;
        __syncthreads();
#pragma unroll
        for (int t=0;t<16;t++){
            float4 qa = *(float4*)&Qs [t][ty*4];
            float4 ka = *(float4*)&Ks [t][tx*4];
            float4 ra = *(float4*)&RQs[t][ty*4];
            float4 rb = *(float4*)&RKs[t][tx*4];
            float qv[4]={qa.x,qa.y,qa.z,qa.w}, kv[4]={ka.x,ka.y,ka.z,ka.w};
            float rv[4]={ra.x,ra.y,ra.z,ra.w}, sv[4]={rb.x,rb.y,rb.z,rb.w};
#pragma unroll
            for (int i=0;i<4;i++)
#pragma unroll
                for (int j=0;j<4;j++){
                    as[i][j] = fmaf(qv[i], kv[j], as[i][j]);
                    ac[i][j] = fmaf(rv[i], sv[j], ac[i][j]);
                }
        }
        __syncthreads();
    }

    float st = strengths[h];
    size_t obase = ((size_t)z*Ss + i0)*Ss + j0;
#pragma unroll
    for (int i=0;i<4;i++){
        float4 o1 = make_float4(as[i][0]*0.125f, as[i][1]*0.125f, as[i][2]*0.125f, as[i][3]*0.125f);
        float4 o2 = make_float4(ac[i][0]*st,     ac[i][1]*st,     ac[i][2]*st,     ac[i][3]*st);
        size_t ro = obase + (size_t)(ty*4+i)*Ss + tx*4;
        *(float4*)(sc + ro) = o1;
        *(float4*)(qc + ro) = o2;
    }
}

// ---------------- fused head-mix + causal softmax ----------------
// block per (b, i): all 16 output heads in registers; reads each qc row once.
// final_g = scores_g + sum_h (delta_hg + 0.1 E[h,g]) * qc_h ; softmax over j<=i.
__global__ void __launch_bounds__(256) softmax_mix_k(
    const float* __restrict__ E, float* __restrict__ sw, const float* __restrict__ qc)
{
    int i = blockIdx.x, b = blockIdx.y;
    int tid = threadIdx.x;
    __shared__ float coef[16][16];
    __shared__ float red[8];
    {
        int h = tid >> 4, g = tid & 15;
        coef[h][g] = ((h==g) ? 1.f : 0.f) + 0.1f * E[h*16 + g];
    }
    __syncthreads();

    bool valid[4];
#pragma unroll
    for (int it=0; it<4; it++) valid[it] = (tid + 256*it) <= i;

    float acc[16][4];
#pragma unroll
    for (int g=0; g<16; g++){
        const float* row = sw + (((size_t)(b*16+g))*Ss + i)*Ss;
#pragma unroll
        for (int it=0; it<4; it++){
            int j = tid + 256*it;
            acc[g][it] = valid[it] ? row[j] : -1e30f;
        }
    }
    for (int h=0; h<16; h++){
        const float* row = qc + (((size_t)(b*16+h))*Ss + i)*Ss;
        float qv[4];
#pragma unroll
        for (int it=0; it<4; it++){
            int j = tid + 256*it;
            qv[it] = valid[it] ? row[j] : 0.f;
        }
#pragma unroll
        for (int g=0; g<16; g++){
            float cf = coef[h][g];
#pragma unroll
            for (int it=0; it<4; it++) acc[g][it] = fmaf(cf, qv[it], acc[g][it]);
        }
    }
#pragma unroll
    for (int g=0; g<16; g++){
        float m = -1e30f;
#pragma unroll
        for (int it=0; it<4; it++) if (valid[it]) m = fmaxf(m, acc[g][it]);
        m = blockMax(m, red);
        float e[4], s = 0.f;
#pragma unroll
        for (int it=0; it<4; it++){
            e[it] = valid[it] ? expf(acc[g][it] - m) : 0.f;
            s += e[it];
        }
        s = blockSum(s, red);
        float inv = 1.f / s;
        float* row = sw + (((size_t)(b*16+g))*Ss + i)*Ss;
#pragma unroll
        for (int it=0; it<4; it++){
            int j = tid + 256*it;
            row[j] = e[it] * inv;   // zeros beyond i -> full row defined for attn@V
        }
    }
}

// ---------------- fused residual-add + LayerNorm ----------------
__global__ void __launch_bounds__(256) add_ln_k(
    const float* __restrict__ xa, const float* __restrict__ xb,
    const float* __restrict__ gamma, const float* __restrict__ beta,
    float* __restrict__ out)
{
    int r = blockIdx.x;
    int tid = threadIdx.x;
    __shared__ float red[8];
    float v[4], s = 0.f, ss = 0.f;
#pragma unroll
    for (int it=0; it<4; it++){
        int idx = tid + 256*it;
        float a = xa[(size_t)r*Dd + idx] + xb[(size_t)r*Dd + idx];
        v[it] = a; s += a; ss += a*a;
    }
    s  = blockSum(s,  red);
    ss = blockSum(ss, red);
    float mu  = s * (1.f/Dd);
    float var = ss * (1.f/Dd) - mu*mu;
    float rs  = rsqrtf(var + 1e-5f);
#pragma unroll
    for (int it=0; it<4; it++){
        int idx = tid + 256*it;
        out[(size_t)r*Dd + idx] = (v[it] - mu) * rs * gamma[idx] + beta[idx];
    }
}

// ---------------- launch ----------------
extern "C" void kernel_launch(void* const* d_in, const int* in_sizes, int n_in,
                              void* d_out, int out_size)
{
    const float* x   = (const float*)d_in[0];
    const float* Wq  = (const float*)d_in[2];
    const float* bq  = (const float*)d_in[3];
    const float* Wk  = (const float*)d_in[4];
    const float* bk  = (const float*)d_in[5];
    const float* Wv  = (const float*)d_in[6];
    const float* bv  = (const float*)d_in[7];
    const float* Wo  = (const float*)d_in[8];
    const float* bo  = (const float*)d_in[9];
    const float* Wt  = (const float*)d_in[10];
    const float* bt  = (const float*)d_in[11];
    const float* E   = (const float*)d_in[12];
    const float* strengths = (const float*)d_in[13];
    const float* W1  = (const float*)d_in[14];
    const float* b1  = (const float*)d_in[15];
    const float* W2  = (const float*)d_in[16];
    const float* b2  = (const float*)d_in[17];
    const float* thf = (const float*)d_in[18];
    const float* g1  = (const float*)d_in[19];
    const float* be1 = (const float*)d_in[20];
    const float* g3  = (const float*)d_in[21];
    const float* be3 = (const float*)d_in[22];
    float* out = (float*)d_out;

    float *pq,*pk,*pv,*prq,*prk,*psc,*pqc,*pattn,*ptmp,*px1,*phh;
    cudaGetSymbolAddress((void**)&pq,   g_q);
    cudaGetSymbolAddress((void**)&pk,   g_k);
    cudaGetSymbolAddress((void**)&pv,   g_v);
    cudaGetSymbolAddress((void**)&prq,  g_rq);
    cudaGetSymbolAddress((void**)&prk,  g_rk);
    cudaGetSymbolAddress((void**)&psc,  g_sc);
    cudaGetSymbolAddress((void**)&pqc,  g_qc);
    cudaGetSymbolAddress((void**)&pattn,g_attn);
    cudaGetSymbolAddress((void**)&ptmp, g_tmp);
    cudaGetSymbolAddress((void**)&px1,  g_x1);
    cudaGetSymbolAddress((void**)&phh,  g_hh);

    dim3 blk(256);
    // QKV projections: [4096,1024] = x @ W^T + b
    gemm_k<0,0><<<dim3(16,32,1), blk>>>(x, Wq, bq, pq, Mrows,Dd,Dd, Dd,Dd,Dd, 0,0,0,0,0,1, nullptr);
    gemm_k<0,0><<<dim3(16,32,1), blk>>>(x, Wk, bk, pk, Mrows,Dd,Dd, Dd,Dd,Dd, 0,0,0,0,0,1, nullptr);
    gemm_k<0,0><<<dim3(16,32,1), blk>>>(x, Wv, bv, pv, Mrows,Dd,Dd, Dd,Dd,Dd, 0,0,0,0,0,1, nullptr);
    // theta projection + r = cos(pi*sigmoid): rows are (b,s,h) 64-chunks
    gemm_k<0,2><<<dim3(1,512,1), blk>>>(pq, Wt, bt, prq, Mrows*Hh,DKk,DKk, DKk,DKk,DKk, 0,0,0,0,0,1, nullptr);
    gemm_k<0,2><<<dim3(1,512,1), blk>>>(pk, Wt, bt, prk, Mrows*Hh,DKk,DKk, DKk,DKk,DKk, 0,0,0,0,0,1, nullptr);
    // scores + qc (causal tile-skipped)
    scores_k<<<dim3(16,16,Bb*Hh), blk>>>(pq, pk, prq, prk, strengths, psc, pqc);
    // head-mix + softmax (in place on scores buffer)
    softmax_mix_k<<<dim3(Ss,Bb), blk>>>(E, psc, pqc);
    // attn = w @ v  (per (b,h), output into [B,S,D] head slices)
    gemm_k<1,0><<<dim3(1,8,Bb*Hh), blk>>>(psc, pv, nullptr, pattn,
        Ss, DKk, Ss, Ss, Dd, Dd,
        (long)Ss*Ss, (long)Ss*Dd, (long)DKk, (long)Ss*Dd, (long)DKk, Hh, nullptr);
    // output projection
    gemm_k<0,0><<<dim3(16,32,1), blk>>>(pattn, Wo, bo, ptmp, Mrows,Dd,Dd, Dd,Dd,Dd, 0,0,0,0,0,1, nullptr);
    // x1 = LN(x + attn_out)
    add_ln_k<<<Mrows, blk>>>(x, ptmp, g1, be1, px1);
    // FFN up (exact GELU * quantum gate fused in epilogue)
    gemm_k<0,1><<<dim3(64,32,1), blk>>>(px1, W1, b1, phh, Mrows,DFFf,Dd, Dd,Dd,DFFf, 0,0,0,0,0,1, thf);
    // FFN down
    gemm_k<0,0><<<dim3(16,32,1), blk>>>(phh, W2, b2, ptmp, Mrows,Dd,DFFf, DFFf,DFFf,Dd, 0,0,0,0,0,1, nullptr);
    // out = LN(x1 + ff)
    add_ln_k<<<Mrows, blk>>>(px1, ptmp, g3, be3, out);
    (void)in_sizes; (void)n_in; (void)out_size;
}

// round 3
// speedup vs baseline: 2.1992x; 2.1992x over previous
#include <cuda_runtime.h>
#include <cuda_bf16.h>
#include <cstdint>
#include <cstddef>

#define Bb   4
#define Ss   1024
#define Dd   1024
#define Hh   16
#define DKk  64
#define DFFf 4096
#define Mrows (Bb*Ss)

// ---------------- scratch (device globals; no allocation) ----------------
__device__ float g_q   [(size_t)Mrows*Dd];
__device__ float g_k   [(size_t)Mrows*Dd];
__device__ float g_v   [(size_t)Mrows*Dd];
__device__ float g_rq  [(size_t)Mrows*Dd];
__device__ float g_rk  [(size_t)Mrows*Dd];
__device__ float g_sc  [(size_t)Bb*Hh*Ss*Ss];   // scores, reused as softmax weights
__device__ float g_qc  [(size_t)Bb*Hh*Ss*Ss];   // quantum bias
__device__ float g_attn[(size_t)Mrows*Dd];
__device__ float g_tmp [(size_t)Mrows*Dd];
__device__ float g_x1  [(size_t)Mrows*Dd];
__device__ float g_hh  [(size_t)Mrows*DFFf];

// ---------------- reductions ----------------
__device__ __forceinline__ float warpSum(float v){
#pragma unroll
    for (int o=16;o;o>>=1) v += __shfl_xor_sync(0xffffffffu, v, o);
    return v;
}
__device__ __forceinline__ float warpMax(float v){
#pragma unroll
    for (int o=16;o;o>>=1) v = fmaxf(v, __shfl_xor_sync(0xffffffffu, v, o));
    return v;
}
__device__ __forceinline__ float blockSum(float v, float* red){
    int lane = threadIdx.x & 31, w = threadIdx.x >> 5;
    v = warpSum(v);
    __syncthreads();
    if (lane == 0) red[w] = v;
    __syncthreads();
    float r = red[0];
#pragma unroll
    for (int i=1;i<8;i++) r += red[i];
    return r;
}
__device__ __forceinline__ float blockMax(float v, float* red){
    int lane = threadIdx.x & 31, w = threadIdx.x >> 5;
    v = warpMax(v);
    __syncthreads();
    if (lane == 0) red[w] = v;
    __syncthreads();
    float r = red[0];
#pragma unroll
    for (int i=1;i<8;i++) r = fmaxf(r, red[i]);
    return r;
}

// ---------------- tensor-core helpers ----------------
__device__ __forceinline__ void ldsm4(uint32_t* r, uint32_t addr){
    asm volatile("ldmatrix.sync.aligned.m8n8.x4.shared.b16 {%0,%1,%2,%3},[%4];"
        : "=r"(r[0]),"=r"(r[1]),"=r"(r[2]),"=r"(r[3]) : "r"(addr));
}
__device__ __forceinline__ void ldsm4t(uint32_t* r, uint32_t addr){
    asm volatile("ldmatrix.sync.aligned.m8n8.x4.trans.shared.b16 {%0,%1,%2,%3},[%4];"
        : "=r"(r[0]),"=r"(r[1]),"=r"(r[2]),"=r"(r[3]) : "r"(addr));
}
__device__ __forceinline__ void mma16816(float* d, const uint32_t* a, uint32_t b0, uint32_t b1){
    asm volatile("mma.sync.aligned.m16n8k16.row.col.f32.bf16.bf16.f32 "
        "{%0,%1,%2,%3},{%4,%5,%6,%7},{%8,%9},{%0,%1,%2,%3};"
        : "+f"(d[0]),"+f"(d[1]),"+f"(d[2]),"+f"(d[3])
        : "r"(a[0]),"r"(a[1]),"r"(a[2]),"r"(a[3]),"r"(b0),"r"(b1));
}
__device__ __forceinline__ uint32_t pack2(__nv_bfloat16 a, __nv_bfloat16 b){
    return (uint32_t)__bfloat16_as_ushort(a) | ((uint32_t)__bfloat16_as_ushort(b) << 16);
}
// split float4 into hi/lo bf16 quads (packed as 2x uint32 each)
__device__ __forceinline__ void split4(float4 v, uint2& hi, uint2& lo){
    __nv_bfloat16 h0=__float2bfloat16(v.x), h1=__float2bfloat16(v.y);
    __nv_bfloat16 h2=__float2bfloat16(v.z), h3=__float2bfloat16(v.w);
    __nv_bfloat16 l0=__float2bfloat16(v.x-__bfloat162float(h0));
    __nv_bfloat16 l1=__float2bfloat16(v.y-__bfloat162float(h1));
    __nv_bfloat16 l2=__float2bfloat16(v.z-__bfloat162float(h2));
    __nv_bfloat16 l3=__float2bfloat16(v.w-__bfloat162float(h3));
    hi.x = pack2(h0,h1); hi.y = pack2(h2,h3);
    lo.x = pack2(l0,l1); lo.y = pack2(l2,l3);
}

// ---------------- tensor-core SGEMM (bf16x3 split): C = A @ B(^T) + bias ----------------
// BMODE 0: B operand is W[N,K] row-major (ldb = K)
// BMODE 1: B operand is matrix [K, N] row-major (ldb)
// EPI 0: none; 1: exact GELU * (1 + 0.1|sin 2*theta|); 2: cos(pi * sigmoid(x))
// Tile: BM=128, BN=64, BK=32. 256 threads = 8 warps (4 m x 2 n), warp tile 32x32.
template<int BMODE, int EPI>
__global__ void __launch_bounds__(256) gemm_k(
    const float* __restrict__ A, const float* __restrict__ Bp,
    const float* __restrict__ bias, float* __restrict__ C,
    int M, int N, int K, int lda, int ldb, int ldc,
    long sA, long sB, long sB2, long sC, long sC2, int Hdim,
    const float* __restrict__ extra)
{
    const int BKP = 40;   // padded row stride (elements) for [rows][k] tiles
    const int BNP = 72;   // padded row stride for [k][n] tiles (BMODE1)

    int z = blockIdx.z;
    const float* Az = A + (long)z * sA;
    long boff, coff;
    if (Hdim > 1) {
        int zb = z / Hdim, zh = z % Hdim;
        boff = (long)zb*sB + (long)zh*sB2;
        coff = (long)zb*sC + (long)zh*sC2;
    } else {
        boff = (long)z*sB;
        coff = (long)z*sC;
    }
    const float* Bz = Bp + boff;
    float* Cz = C + coff;

    int n0 = blockIdx.x * 64;
    int m0 = blockIdx.y * 128;
    int tid = threadIdx.x;
    int lane = tid & 31;
    int w = tid >> 5;
    int wm = w & 3;        // 0..3  (m warp tile of 32)
    int wn = w >> 2;       // 0..1  (n warp tile of 32)

    __shared__ __align__(16) __nv_bfloat16 AsH[128*BKP];
    __shared__ __align__(16) __nv_bfloat16 AsL[128*BKP];
    __shared__ __align__(16) __nv_bfloat16 BsH[2560];   // max(64*40, 32*72)
    __shared__ __align__(16) __nv_bfloat16 BsL[2560];

    float acc[2][4][4];
#pragma unroll
    for (int i=0;i<2;i++)
#pragma unroll
        for (int j=0;j<4;j++)
#pragma unroll
            for (int q=0;q<4;q++) acc[i][j][q] = 0.f;

    // ---- gmem staging regs ----
    float4 av[4];
    float4 bv[2];
    int arow = tid >> 3;           // 0..31
    int acol = (tid & 7) * 4;      // 0..28

    // precompute ldmatrix base coords
    int a_r = wm*32 + (lane & 7) + ((lane >> 3) & 1) * 8;     // + mi*16
    int a_c = (lane >> 4) * 8;                                 // + ks*16
    int b0_r = wn*32 + (lane & 7) + ((lane >= 16) ? 8 : 0);    // + nt*16 (BMODE0)
    int b0_c = ((lane >> 3) & 1) * 8;                          // + ks*16
    int b1_r = (lane & 7) + ((lane >> 3) & 1) * 8;             // + ks*16 (BMODE1, k rows)
    int b1_c = wn*32 + ((lane >= 16) ? 8 : 0);                 // + nt*16

    uint32_t sAH = (uint32_t)__cvta_generic_to_shared(AsH);
    uint32_t sAL = (uint32_t)__cvta_generic_to_shared(AsL);
    uint32_t sBH = (uint32_t)__cvta_generic_to_shared(BsH);
    uint32_t sBL = (uint32_t)__cvta_generic_to_shared(BsL);

    // ---- prologue: load k0=0 ----
#pragma unroll
    for (int i=0;i<4;i++)
        av[i] = *(const float4*)(Az + (size_t)(m0 + i*32 + arow)*lda + acol);
    if (BMODE == 0){
#pragma unroll
        for (int i=0;i<2;i++)
            bv[i] = *(const float4*)(Bz + (size_t)(n0 + i*32 + arow)*ldb + acol);
    } else {
#pragma unroll
        for (int i=0;i<2;i++)
            bv[i] = *(const float4*)(Bz + (size_t)(i*16 + (tid>>4))*ldb + n0 + (tid&15)*4);
    }
    // store to smem
    {
#pragma unroll
        for (int i=0;i<4;i++){
            uint2 hi, lo; split4(av[i], hi, lo);
            int r = i*32 + arow;
            *(uint2*)&AsH[r*BKP + acol] = hi;
            *(uint2*)&AsL[r*BKP + acol] = lo;
        }
        if (BMODE == 0){
#pragma unroll
            for (int i=0;i<2;i++){
                uint2 hi, lo; split4(bv[i], hi, lo);
                int r = i*32 + arow;
                *(uint2*)&BsH[r*BKP + acol] = hi;
                *(uint2*)&BsL[r*BKP + acol] = lo;
            }
        } else {
#pragma unroll
            for (int i=0;i<2;i++){
                uint2 hi, lo; split4(bv[i], hi, lo);
                int r = i*16 + (tid>>4), c = (tid&15)*4;
                *(uint2*)&BsH[r*BNP + c] = hi;
                *(uint2*)&BsL[r*BNP + c] = lo;
            }
        }
    }
    __syncthreads();

    for (int k0 = 0;;) {
        int kn = k0 + 32;
        bool more = kn < K;
        if (more){
#pragma unroll
            for (int i=0;i<4;i++)
                av[i] = *(const float4*)(Az + (size_t)(m0 + i*32 + arow)*lda + kn + acol);
            if (BMODE == 0){
#pragma unroll
                for (int i=0;i<2;i++)
                    bv[i] = *(const float4*)(Bz + (size_t)(n0 + i*32 + arow)*ldb + kn + acol);
            } else {
#pragma unroll
                for (int i=0;i<2;i++)
                    bv[i] = *(const float4*)(Bz + (size_t)(kn + i*16 + (tid>>4))*ldb + n0 + (tid&15)*4);
            }
        }

        // ---- compute 2 k16 steps, 3 split passes each ----
#pragma unroll
        for (int ks=0; ks<2; ks++){
            uint32_t ah[2][4], al[2][4], bh[2][4], bl[2][4];
#pragma unroll
            for (int mi=0; mi<2; mi++){
                uint32_t off = (uint32_t)((a_r + mi*16)*BKP + a_c + ks*16) * 2;
                ldsm4(ah[mi], sAH + off);
                ldsm4(al[mi], sAL + off);
            }
            if (BMODE == 0){
#pragma unroll
                for (int nt=0; nt<2; nt++){
                    uint32_t off = (uint32_t)((b0_r + nt*16)*BKP + b0_c + ks*16) * 2;
                    ldsm4(bh[nt], sBH + off);
                    ldsm4(bl[nt], sBL + off);
                }
            } else {
#pragma unroll
                for (int nt=0; nt<2; nt++){
                    uint32_t off = (uint32_t)((b1_r + ks*16)*BNP + b1_c + nt*16) * 2;
                    ldsm4t(bh[nt], sBH + off);
                    ldsm4t(bl[nt], sBL + off);
                }
            }
            // pass 1: Ah * Bh ; pass 2: Ah * Bl ; pass 3: Al * Bh
#pragma unroll
            for (int mi=0; mi<2; mi++)
#pragma unroll
                for (int ni=0; ni<4; ni++){
                    const uint32_t* bq = &bh[ni>>1][(ni&1)*2];
                    mma16816(acc[mi][ni], ah[mi], bq[0], bq[1]);
                }
#pragma unroll
            for (int mi=0; mi<2; mi++)
#pragma unroll
                for (int ni=0; ni<4; ni++){
                    const uint32_t* bq = &bl[ni>>1][(ni&1)*2];
                    mma16816(acc[mi][ni], ah[mi], bq[0], bq[1]);
                }
#pragma unroll
            for (int mi=0; mi<2; mi++)
#pragma unroll
                for (int ni=0; ni<4; ni++){
                    const uint32_t* bq = &bh[ni>>1][(ni&1)*2];
                    mma16816(acc[mi][ni], al[mi], bq[0], bq[1]);
                }
        }

        if (!more) break;
        __syncthreads();
        {
#pragma unroll
            for (int i=0;i<4;i++){
                uint2 hi, lo; split4(av[i], hi, lo);
                int r = i*32 + arow;
                *(uint2*)&AsH[r*BKP + acol] = hi;
                *(uint2*)&AsL[r*BKP + acol] = lo;
            }
            if (BMODE == 0){
#pragma unroll
                for (int i=0;i<2;i++){
                    uint2 hi, lo; split4(bv[i], hi, lo);
                    int r = i*32 + arow;
                    *(uint2*)&BsH[r*BKP + acol] = hi;
                    *(uint2*)&BsL[r*BKP + acol] = lo;
                }
            } else {
#pragma unroll
                for (int i=0;i<2;i++){
                    uint2 hi, lo; split4(bv[i], hi, lo);
                    int r = i*16 + (tid>>4), c = (tid&15)*4;
                    *(uint2*)&BsH[r*BNP + c] = hi;
                    *(uint2*)&BsL[r*BNP + c] = lo;
                }
            }
        }
        __syncthreads();
        k0 = kn;
    }

    // ---- epilogue ----
    int g = lane >> 2, t2 = (lane & 3) * 2;
#pragma unroll
    for (int mi=0; mi<2; mi++){
        int r0 = m0 + wm*32 + mi*16 + g;
#pragma unroll
        for (int ni=0; ni<4; ni++){
            int c0 = n0 + wn*32 + ni*8 + t2;
            float b0v = bias ? bias[c0]   : 0.f;
            float b1v = bias ? bias[c0+1] : 0.f;
            float v[4];
            v[0] = acc[mi][ni][0] + b0v;
            v[1] = acc[mi][ni][1] + b1v;
            v[2] = acc[mi][ni][2] + b0v;
            v[3] = acc[mi][ni][3] + b1v;
            if (EPI == 1){
                float th0 = extra[c0], th1 = extra[c0+1];
                float q0 = 1.f + 0.1f * fabsf(sinf(2.f*th0));
                float q1 = 1.f + 0.1f * fabsf(sinf(2.f*th1));
#pragma unroll
                for (int q=0;q<4;q++){
                    float ge = 0.5f * v[q] * (1.f + erff(v[q] * 0.70710678118654752f));
                    v[q] = ge * ((q&1) ? q1 : q0);
                }
            } else if (EPI == 2){
#pragma unroll
                for (int q=0;q<4;q++){
                    float s = 1.f / (1.f + expf(-v[q]));
                    v[q] = cospif(s);
                }
            }
            *(float2*)(Cz + (size_t)r0*ldc + c0)     = make_float2(v[0], v[1]);
            *(float2*)(Cz + (size_t)(r0+8)*ldc + c0) = make_float2(v[2], v[3]);
        }
    }
}

// ---------------- fused scores + quantum-correlation kernel ----------------
__global__ void __launch_bounds__(256) scores_k(
    const float* __restrict__ q, const float* __restrict__ kmat,
    const float* __restrict__ rq, const float* __restrict__ rk,
    const float* __restrict__ strengths,
    float* __restrict__ sc, float* __restrict__ qc)
{
    int bj = blockIdx.x, bi = blockIdx.y;
    if (bj > bi) return;                       // fully masked tile
    int z = blockIdx.z;
    int b = z >> 4, h = z & 15;
    int i0 = bi*64, j0 = bj*64;
    size_t base = (size_t)b*Ss*Dd + (size_t)h*DKk;

    __shared__ float Qs[16][64], Ks[16][64], RQs[16][64], RKs[16][64];
    int tid = threadIdx.x;
    int tx = tid & 15, ty = tid >> 4;
    int m  = tid >> 2;
    int kq = (tid & 3) * 4;

    float as[4][4], ac[4][4];
#pragma unroll
    for (int i=0;i<4;i++)
#pragma unroll
        for (int j=0;j<4;j++){ as[i][j]=0.f; ac[i][j]=0.f; }

    for (int k0=0; k0<64; k0+=16){
        float4 a = *(const float4*)(q    + base + (size_t)(i0+m)*Dd + k0 + kq);
        float4 c = *(const float4*)(rq   + base + (size_t)(i0+m)*Dd + k0 + kq);
        float4 d = *(const float4*)(kmat + base + (size_t)(j0+m)*Dd + k0 + kq);
        float4 e = *(const float4*)(rk   + base + (size_t)(j0+m)*Dd + k0 + kq);
        Qs [kq+0][m]=a.x; Qs [kq+1][m]=a.y; Qs [kq+2][m]=a.z; Qs [kq+3][m]=a.w;
        RQs[kq+0][m]=c.x; RQs[kq+1][m]=c.y; RQs[kq+2][m]=c.z; RQs[kq+3][m]=c.w;
        Ks [kq+0][m]=d.x; Ks [kq+1][m]=d.y; Ks [kq+2][m]=d.z; Ks [kq+3][m]=d.w;
        RKs[kq+0][m]=e.x; RKs[kq+1][m]=e.y; RKs[kq+2][m]=e.z; RKs[kq+3][m]=e.w;
        __syncthreads();
#pragma unroll
        for (int t=0;t<16;t++){
            float4 qa = *(float4*)&Qs [t][ty*4];
            float4 ka = *(float4*)&Ks [t][tx*4];
            float4 ra = *(float4*)&RQs[t][ty*4];
            float4 rb = *(float4*)&RKs[t][tx*4];
            float qv[4]={qa.x,qa.y,qa.z,qa.w}, kv[4]={ka.x,ka.y,ka.z,ka.w};
            float rv[4]={ra.x,ra.y,ra.z,ra.w}, sv[4]={rb.x,rb.y,rb.z,rb.w};
#pragma unroll
            for (int i=0;i<4;i++)
#pragma unroll
                for (int j=0;j<4;j++){
                    as[i][j] = fmaf(qv[i], kv[j], as[i][j]);
                    ac[i][j] = fmaf(rv[i], sv[j], ac[i][j]);
                }
        }
        __syncthreads();
    }

    float st = strengths[h];
    size_t obase = ((size_t)z*Ss + i0)*Ss + j0;
#pragma unroll
    for (int i=0;i<4;i++){
        float4 o1 = make_float4(as[i][0]*0.125f, as[i][1]*0.125f, as[i][2]*0.125f, as[i][3]*0.125f);
        float4 o2 = make_float4(ac[i][0]*st,     ac[i][1]*st,     ac[i][2]*st,     ac[i][3]*st);
        size_t ro = obase + (size_t)(ty*4+i)*Ss + tx*4;
        *(float4*)(sc + ro) = o1;
        *(float4*)(qc + ro) = o2;
    }
}

// ---------------- fused head-mix + causal softmax ----------------
__global__ void __launch_bounds__(256) softmax_mix_k(
    const float* __restrict__ E, float* __restrict__ sw, const float* __restrict__ qc)
{
    int i = blockIdx.x, b = blockIdx.y;
    int tid = threadIdx.x;
    __shared__ float coef[16][16];
    __shared__ float red[8];
    {
        int h = tid >> 4, g = tid & 15;
        coef[h][g] = ((h==g) ? 1.f : 0.f) + 0.1f * E[h*16 + g];
    }
    __syncthreads();

    bool valid[4];
#pragma unroll
    for (int it=0; it<4; it++) valid[it] = (tid + 256*it) <= i;

    float acc[16][4];
#pragma unroll
    for (int g=0; g<16; g++){
        const float* row = sw + (((size_t)(b*16+g))*Ss + i)*Ss;
#pragma unroll
        for (int it=0; it<4; it++){
            int j = tid + 256*it;
            acc[g][it] = valid[it] ? row[j] : -1e30f;
        }
    }
    for (int h=0; h<16; h++){
        const float* row = qc + (((size_t)(b*16+h))*Ss + i)*Ss;
        float qv[4];
#pragma unroll
        for (int it=0; it<4; it++){
            int j = tid + 256*it;
            qv[it] = valid[it] ? row[j] : 0.f;
        }
#pragma unroll
        for (int g=0; g<16; g++){
            float cf = coef[h][g];
#pragma unroll
            for (int it=0; it<4; it++) acc[g][it] = fmaf(cf, qv[it], acc[g][it]);
        }
    }
#pragma unroll
    for (int g=0; g<16; g++){
        float m = -1e30f;
#pragma unroll
        for (int it=0; it<4; it++) if (valid[it]) m = fmaxf(m, acc[g][it]);
        m = blockMax(m, red);
        float e[4], s = 0.f;
#pragma unroll
        for (int it=0; it<4; it++){
            e[it] = valid[it] ? expf(acc[g][it] - m) : 0.f;
            s += e[it];
        }
        s = blockSum(s, red);
        float inv = 1.f / s;
        float* row = sw + (((size_t)(b*16+g))*Ss + i)*Ss;
#pragma unroll
        for (int it=0; it<4; it++){
            int j = tid + 256*it;
            row[j] = e[it] * inv;
        }
    }
}

// ---------------- fused residual-add + LayerNorm ----------------
__global__ void __launch_bounds__(256) add_ln_k(
    const float* __restrict__ xa, const float* __restrict__ xb,
    const float* __restrict__ gamma, const float* __restrict__ beta,
    float* __restrict__ out)
{
    int r = blockIdx.x;
    int tid = threadIdx.x;
    __shared__ float red[8];
    float v[4], s = 0.f, ss = 0.f;
#pragma unroll
    for (int it=0; it<4; it++){
        int idx = tid + 256*it;
        float a = xa[(size_t)r*Dd + idx] + xb[(size_t)r*Dd + idx];
        v[it] = a; s += a; ss += a*a;
    }
    s  = blockSum(s,  red);
    ss = blockSum(ss, red);
    float mu  = s * (1.f/Dd);
    float var = ss * (1.f/Dd) - mu*mu;
    float rs  = rsqrtf(var + 1e-5f);
#pragma unroll
    for (int it=0; it<4; it++){
        int idx = tid + 256*it;
        out[(size_t)r*Dd + idx] = (v[it] - mu) * rs * gamma[idx] + beta[idx];
    }
}

// ---------------- launch ----------------
extern "C" void kernel_launch(void* const* d_in, const int* in_sizes, int n_in,
                              void* d_out, int out_size)
{
    const float* x   = (const float*)d_in[0];
    const float* Wq  = (const float*)d_in[2];
    const float* bq  = (const float*)d_in[3];
    const float* Wk  = (const float*)d_in[4];
    const float* bk  = (const float*)d_in[5];
    const float* Wv  = (const float*)d_in[6];
    const float* bv  = (const float*)d_in[7];
    const float* Wo  = (const float*)d_in[8];
    const float* bo  = (const float*)d_in[9];
    const float* Wt  = (const float*)d_in[10];
    const float* bt  = (const float*)d_in[11];
    const float* E   = (const float*)d_in[12];
    const float* strengths = (const float*)d_in[13];
    const float* W1  = (const float*)d_in[14];
    const float* b1  = (const float*)d_in[15];
    const float* W2  = (const float*)d_in[16];
    const float* b2  = (const float*)d_in[17];
    const float* thf = (const float*)d_in[18];
    const float* g1  = (const float*)d_in[19];
    const float* be1 = (const float*)d_in[20];
    const float* g3  = (const float*)d_in[21];
    const float* be3 = (const float*)d_in[22];
    float* out = (float*)d_out;

    float *pq,*pk,*pv,*prq,*prk,*psc,*pqc,*pattn,*ptmp,*px1,*phh;
    cudaGetSymbolAddress((void**)&pq,   g_q);
    cudaGetSymbolAddress((void**)&pk,   g_k);
    cudaGetSymbolAddress((void**)&pv,   g_v);
    cudaGetSymbolAddress((void**)&prq,  g_rq);
    cudaGetSymbolAddress((void**)&prk,  g_rk);
    cudaGetSymbolAddress((void**)&psc,  g_sc);
    cudaGetSymbolAddress((void**)&pqc,  g_qc);
    cudaGetSymbolAddress((void**)&pattn,g_attn);
    cudaGetSymbolAddress((void**)&ptmp, g_tmp);
    cudaGetSymbolAddress((void**)&px1,  g_x1);
    cudaGetSymbolAddress((void**)&phh,  g_hh);

    dim3 blk(256);
    // QKV projections
    gemm_k<0,0><<<dim3(16,32,1), blk>>>(x, Wq, bq, pq, Mrows,Dd,Dd, Dd,Dd,Dd, 0,0,0,0,0,1, nullptr);
    gemm_k<0,0><<<dim3(16,32,1), blk>>>(x, Wk, bk, pk, Mrows,Dd,Dd, Dd,Dd,Dd, 0,0,0,0,0,1, nullptr);
    gemm_k<0,0><<<dim3(16,32,1), blk>>>(x, Wv, bv, pv, Mrows,Dd,Dd, Dd,Dd,Dd, 0,0,0,0,0,1, nullptr);
    // theta projection + r = cos(pi*sigmoid)
    gemm_k<0,2><<<dim3(1,512,1), blk>>>(pq, Wt, bt, prq, Mrows*Hh,DKk,DKk, DKk,DKk,DKk, 0,0,0,0,0,1, nullptr);
    gemm_k<0,2><<<dim3(1,512,1), blk>>>(pk, Wt, bt, prk, Mrows*Hh,DKk,DKk, DKk,DKk,DKk, 0,0,0,0,0,1, nullptr);
    // scores + qc (causal tile-skipped)
    scores_k<<<dim3(16,16,Bb*Hh), blk>>>(pq, pk, prq, prk, strengths, psc, pqc);
    // head-mix + softmax (in place on scores buffer)
    softmax_mix_k<<<dim3(Ss,Bb), blk>>>(E, psc, pqc);
    // attn = w @ v
    gemm_k<1,0><<<dim3(1,8,Bb*Hh), blk>>>(psc, pv, nullptr, pattn,
        Ss, DKk, Ss, Ss, Dd, Dd,
        (long)Ss*Ss, (long)Ss*Dd, (long)DKk, (long)Ss*Dd, (long)DKk, Hh, nullptr);
    // output projection
    gemm_k<0,0><<<dim3(16,32,1), blk>>>(pattn, Wo, bo, ptmp, Mrows,Dd,Dd, Dd,Dd,Dd, 0,0,0,0,0,1, nullptr);
    // x1 = LN(x + attn_out)
    add_ln_k<<<Mrows, blk>>>(x, ptmp, g1, be1, px1);
    // FFN up (exact GELU * quantum gate fused in epilogue)
    gemm_k<0,1><<<dim3(64,32,1), blk>>>(px1, W1, b1, phh, Mrows,DFFf,Dd, Dd,Dd,DFFf, 0,0,0,0,0,1, thf);
    // FFN down
    gemm_k<0,0><<<dim3(16,32,1), blk>>>(phh, W2, b2, ptmp, Mrows,Dd,DFFf, DFFf,DFFf,Dd, 0,0,0,0,0,1, nullptr);
    // out = LN(x1 + ff)
    add_ln_k<<<Mrows, blk>>>(px1, ptmp, g3, be3, out);
    (void)in_sizes; (void)n_in; (void)out_size;
}

// round 7
// speedup vs baseline: 2.3480x; 1.0676x over previous
#include <cuda_runtime.h>
#include <cuda_bf16.h>
#include <cstdint>
#include <cstddef>

#define Bb   4
#define Ss   1024
#define Dd   1024
#define Hh   16
#define DKk  64
#define DFFf 4096
#define Mrows (Bb*Ss)

// ---------------- scratch (device globals; no allocation) ----------------
__device__ float g_q   [(size_t)Mrows*Dd];
__device__ float g_k   [(size_t)Mrows*Dd];
__device__ float g_v   [(size_t)Mrows*Dd];
__device__ float g_rq  [(size_t)Mrows*Dd];
__device__ float g_rk  [(size_t)Mrows*Dd];
__device__ float g_sc  [(size_t)Bb*Hh*Ss*Ss];   // scores, reused as softmax weights
__device__ float g_qc  [(size_t)Bb*Hh*Ss*Ss];   // quantum bias
__device__ float g_attn[(size_t)Mrows*Dd];
__device__ float g_tmp [(size_t)Mrows*Dd];
__device__ float g_x1  [(size_t)Mrows*Dd];
__device__ float g_hh  [(size_t)Mrows*DFFf];

// ---------------- reductions ----------------
__device__ __forceinline__ float warpSum(float v){
#pragma unroll
    for (int o=16;o;o>>=1) v += __shfl_xor_sync(0xffffffffu, v, o);
    return v;
}
__device__ __forceinline__ float warpMax(float v){
#pragma unroll
    for (int o=16;o;o>>=1) v = fmaxf(v, __shfl_xor_sync(0xffffffffu, v, o));
    return v;
}
__device__ __forceinline__ float blockSum(float v, float* red){
    int lane = threadIdx.x & 31, w = threadIdx.x >> 5;
    v = warpSum(v);
    __syncthreads();
    if (lane == 0) red[w] = v;
    __syncthreads();
    float r = red[0];
#pragma unroll
    for (int i=1;i<8;i++) r += red[i];
    return r;
}
__device__ __forceinline__ float blockMax(float v, float* red){
    int lane = threadIdx.x & 31, w = threadIdx.x >> 5;
    v = warpMax(v);
    __syncthreads();
    if (lane == 0) red[w] = v;
    __syncthreads();
    float r = red[0];
#pragma unroll
    for (int i=1;i<8;i++) r = fmaxf(r, red[i]);
    return r;
}

// ---------------- tensor-core helpers ----------------
__device__ __forceinline__ void ldsm4(uint32_t* r, uint32_t addr){
    asm volatile("ldmatrix.sync.aligned.m8n8.x4.shared.b16 {%0,%1,%2,%3},[%4];"
        : "=r"(r[0]),"=r"(r[1]),"=r"(r[2]),"=r"(r[3]) : "r"(addr));
}
__device__ __forceinline__ void ldsm4t(uint32_t* r, uint32_t addr){
    asm volatile("ldmatrix.sync.aligned.m8n8.x4.trans.shared.b16 {%0,%1,%2,%3},[%4];"
        : "=r"(r[0]),"=r"(r[1]),"=r"(r[2]),"=r"(r[3]) : "r"(addr));
}
__device__ __forceinline__ void mma16816(float* d, const uint32_t* a, uint32_t b0, uint32_t b1){
    asm volatile("mma.sync.aligned.m16n8k16.row.col.f32.bf16.bf16.f32 "
        "{%0,%1,%2,%3},{%4,%5,%6,%7},{%8,%9},{%0,%1,%2,%3};"
        : "+f"(d[0]),"+f"(d[1]),"+f"(d[2]),"+f"(d[3])
        : "r"(a[0]),"r"(a[1]),"r"(a[2]),"r"(a[3]),"r"(b0),"r"(b1));
}
__device__ __forceinline__ uint32_t pack2(__nv_bfloat16 a, __nv_bfloat16 b){
    return (uint32_t)__bfloat16_as_ushort(a) | ((uint32_t)__bfloat16_as_ushort(b) << 16);
}
__device__ __forceinline__ void split4(float4 v, uint2& hi, uint2& lo){
    __nv_bfloat16 h0=__float2bfloat16(v.x), h1=__float2bfloat16(v.y);
    __nv_bfloat16 h2=__float2bfloat16(v.z), h3=__float2bfloat16(v.w);
    __nv_bfloat16 l0=__float2bfloat16(v.x-__bfloat162float(h0));
    __nv_bfloat16 l1=__float2bfloat16(v.y-__bfloat162float(h1));
    __nv_bfloat16 l2=__float2bfloat16(v.z-__bfloat162float(h2));
    __nv_bfloat16 l3=__float2bfloat16(v.w-__bfloat162float(h3));
    hi.x = pack2(h0,h1); hi.y = pack2(h2,h3);
    lo.x = pack2(l0,l1); lo.y = pack2(l2,l3);
}

// ---------------- tensor-core SGEMM (bf16x3 split): C = A @ B(^T) + bias ----------------
// BMODE 0: B operand is W[N,K] row-major (ldb = K)
// BMODE 1: B operand is matrix [K, N] row-major (ldb)
// EPI 0: none; 1: GELU*(1+0.1|sin 2theta|); 2: cos(pi*sigmoid(x)); 3: scale
// CAUSAL 1: skip tiles with n0 > m0+127 (output in causal-masked region)
// TRIK 1: k-loop stops at m0+128 (A columns beyond are zero: causal weights)
// Tile: BM=128, BN=64, BK=32. 256 threads = 8 warps (4 m x 2 n), warp tile 32x32.
template<int BMODE, int EPI, int CAUSAL, int TRIK>
__global__ void __launch_bounds__(256) gemm_k(
    const float* __restrict__ A, const float* __restrict__ Bp,
    const float* __restrict__ bias, float* __restrict__ C,
    int M, int N, int K, int lda, int ldb, int ldc,
    long sA, long sA2, long sB, long sB2, long sC, long sC2, int Hdim,
    const float* __restrict__ extra, float cscale)
{
    const int BKP = 40;
    const int BNP = 72;

    int n0 = blockIdx.x * 64;
    int m0 = blockIdx.y * 128;
    if (CAUSAL && n0 > m0 + 127) return;

    int z = blockIdx.z;
    int zh = (Hdim > 1) ? (z % Hdim) : 0;
    const float* Az;
    long boff, coff;
    if (Hdim > 1) {
        int zb = z / Hdim;
        Az   = A + (long)zb*sA + (long)zh*sA2;
        boff = (long)zb*sB + (long)zh*sB2;
        coff = (long)zb*sC + (long)zh*sC2;
    } else {
        Az   = A + (long)z*sA;
        boff = (long)z*sB;
        coff = (long)z*sC;
    }
    const float* Bz = Bp + boff;
    float* Cz = C + coff;

    int Keff = K;
    if (TRIK) { Keff = m0 + 128; if (Keff > K) Keff = K; }

    int tid = threadIdx.x;
    int lane = tid & 31;
    int w = tid >> 5;
    int wm = w & 3;
    int wn = w >> 2;

    __shared__ __align__(16) __nv_bfloat16 AsH[128*BKP];
    __shared__ __align__(16) __nv_bfloat16 AsL[128*BKP];
    __shared__ __align__(16) __nv_bfloat16 BsH[2560];
    __shared__ __align__(16) __nv_bfloat16 BsL[2560];

    float acc[2][4][4];
#pragma unroll
    for (int i=0;i<2;i++)
#pragma unroll
        for (int j=0;j<4;j++)
#pragma unroll
            for (int q=0;q<4;q++) acc[i][j][q] = 0.f;

    float4 av[4];
    float4 bv[2];
    int arow = tid >> 3;
    int acol = (tid & 7) * 4;

    int a_r = wm*32 + (lane & 7) + ((lane >> 3) & 1) * 8;
    int a_c = (lane >> 4) * 8;
    int b0_r = wn*32 + (lane & 7) + ((lane >= 16) ? 8 : 0);
    int b0_c = ((lane >> 3) & 1) * 8;
    int b1_r = (lane & 7) + ((lane >> 3) & 1) * 8;
    int b1_c = wn*32 + ((lane >= 16) ? 8 : 0);

    uint32_t sAH = (uint32_t)__cvta_generic_to_shared(AsH);
    uint32_t sAL = (uint32_t)__cvta_generic_to_shared(AsL);
    uint32_t sBH = (uint32_t)__cvta_generic_to_shared(BsH);
    uint32_t sBL = (uint32_t)__cvta_generic_to_shared(BsL);

#pragma unroll
    for (int i=0;i<4;i++)
        av[i] = *(const float4*)(Az + (size_t)(m0 + i*32 + arow)*lda + acol);
    if (BMODE == 0){
#pragma unroll
        for (int i=0;i<2;i++)
            bv[i] = *(const float4*)(Bz + (size_t)(n0 + i*32 + arow)*ldb + acol);
    } else {
#pragma unroll
        for (int i=0;i<2;i++)
            bv[i] = *(const float4*)(Bz + (size_t)(i*16 + (tid>>4))*ldb + n0 + (tid&15)*4);
    }
    {
#pragma unroll
        for (int i=0;i<4;i++){
            uint2 hi, lo; split4(av[i], hi, lo);
            int r = i*32 + arow;
            *(uint2*)&AsH[r*BKP + acol] = hi;
            *(uint2*)&AsL[r*BKP + acol] = lo;
        }
        if (BMODE == 0){
#pragma unroll
            for (int i=0;i<2;i++){
                uint2 hi, lo; split4(bv[i], hi, lo);
                int r = i*32 + arow;
                *(uint2*)&BsH[r*BKP + acol] = hi;
                *(uint2*)&BsL[r*BKP + acol] = lo;
            }
        } else {
#pragma unroll
            for (int i=0;i<2;i++){
                uint2 hi, lo; split4(bv[i], hi, lo);
                int r = i*16 + (tid>>4), c = (tid&15)*4;
                *(uint2*)&BsH[r*BNP + c] = hi;
                *(uint2*)&BsL[r*BNP + c] = lo;
            }
        }
    }
    __syncthreads();

    for (int k0 = 0;;) {
        int kn = k0 + 32;
        bool more = kn < Keff;
        if (more){
#pragma unroll
            for (int i=0;i<4;i++)
                av[i] = *(const float4*)(Az + (size_t)(m0 + i*32 + arow)*lda + kn + acol);
            if (BMODE == 0){
#pragma unroll
                for (int i=0;i<2;i++)
                    bv[i] = *(const float4*)(Bz + (size_t)(n0 + i*32 + arow)*ldb + kn + acol);
            } else {
#pragma unroll
                for (int i=0;i<2;i++)
                    bv[i] = *(const float4*)(Bz + (size_t)(kn + i*16 + (tid>>4))*ldb + n0 + (tid&15)*4);
            }
        }

#pragma unroll
        for (int ks=0; ks<2; ks++){
            uint32_t ah[2][4], al[2][4], bh[2][4], bl[2][4];
#pragma unroll
            for (int mi=0; mi<2; mi++){
                uint32_t off = (uint32_t)((a_r + mi*16)*BKP + a_c + ks*16) * 2;
                ldsm4(ah[mi], sAH + off);
                ldsm4(al[mi], sAL + off);
            }
            if (BMODE == 0){
#pragma unroll
                for (int nt=0; nt<2; nt++){
                    uint32_t off = (uint32_t)((b0_r + nt*16)*BKP + b0_c + ks*16) * 2;
                    ldsm4(bh[nt], sBH + off);
                    ldsm4(bl[nt], sBL + off);
                }
            } else {
#pragma unroll
                for (int nt=0; nt<2; nt++){
                    uint32_t off = (uint32_t)((b1_r + ks*16)*BNP + b1_c + nt*16) * 2;
                    ldsm4t(bh[nt], sBH + off);
                    ldsm4t(bl[nt], sBL + off);
                }
            }
#pragma unroll
            for (int mi=0; mi<2; mi++)
#pragma unroll
                for (int ni=0; ni<4; ni++){
                    const uint32_t* bq = &bh[ni>>1][(ni&1)*2];
                    mma16816(acc[mi][ni], ah[mi], bq[0], bq[1]);
                }
#pragma unroll
            for (int mi=0; mi<2; mi++)
#pragma unroll
                for (int ni=0; ni<4; ni++){
                    const uint32_t* bq = &bl[ni>>1][(ni&1)*2];
                    mma16816(acc[mi][ni], ah[mi], bq[0], bq[1]);
                }
#pragma unroll
            for (int mi=0; mi<2; mi++)
#pragma unroll
                for (int ni=0; ni<4; ni++){
                    const uint32_t* bq = &bh[ni>>1][(ni&1)*2];
                    mma16816(acc[mi][ni], al[mi], bq[0], bq[1]);
                }
        }

        if (!more) break;
        __syncthreads();
        {
#pragma unroll
            for (int i=0;i<4;i++){
                uint2 hi, lo; split4(av[i], hi, lo);
                int r = i*32 + arow;
                *(uint2*)&AsH[r*BKP + acol] = hi;
                *(uint2*)&AsL[r*BKP + acol] = lo;
            }
            if (BMODE == 0){
#pragma unroll
                for (int i=0;i<2;i++){
                    uint2 hi, lo; split4(bv[i], hi, lo);
                    int r = i*32 + arow;
                    *(uint2*)&BsH[r*BKP + acol] = hi;
                    *(uint2*)&BsL[r*BKP + acol] = lo;
                }
            } else {
#pragma unroll
                for (int i=0;i<2;i++){
                    uint2 hi, lo; split4(bv[i], hi, lo);
                    int r = i*16 + (tid>>4), c = (tid&15)*4;
                    *(uint2*)&BsH[r*BNP + c] = hi;
                    *(uint2*)&BsL[r*BNP + c] = lo;
                }
            }
        }
        __syncthreads();
        k0 = kn;
    }

    // ---- epilogue ----
    float scal = 1.f;
    if (EPI == 3) scal = cscale * (extra ? extra[zh] : 1.f);
    int g = lane >> 2, t2 = (lane & 3) * 2;
#pragma unroll
    for (int mi=0; mi<2; mi++){
        int r0 = m0 + wm*32 + mi*16 + g;
#pragma unroll
        for (int ni=0; ni<4; ni++){
            int c0 = n0 + wn*32 + ni*8 + t2;
            float b0v = bias ? bias[c0]   : 0.f;
            float b1v = bias ? bias[c0+1] : 0.f;
            float v[4];
            v[0] = acc[mi][ni][0] + b0v;
            v[1] = acc[mi][ni][1] + b1v;
            v[2] = acc[mi][ni][2] + b0v;
            v[3] = acc[mi][ni][3] + b1v;
            if (EPI == 1){
                float th0 = extra[c0], th1 = extra[c0+1];
                float q0 = 1.f + 0.1f * fabsf(sinf(2.f*th0));
                float q1 = 1.f + 0.1f * fabsf(sinf(2.f*th1));
#pragma unroll
                for (int q=0;q<4;q++){
                    float ge = 0.5f * v[q] * (1.f + erff(v[q] * 0.70710678118654752f));
                    v[q] = ge * ((q&1) ? q1 : q0);
                }
            } else if (EPI == 2){
#pragma unroll
                for (int q=0;q<4;q++){
                    float s = 1.f / (1.f + expf(-v[q]));
                    v[q] = cospif(s);
                }
            } else if (EPI == 3){
#pragma unroll
                for (int q=0;q<4;q++) v[q] *= scal;
            }
            *(float2*)(Cz + (size_t)r0*ldc + c0)     = make_float2(v[0], v[1]);
            *(float2*)(Cz + (size_t)(r0+8)*ldc + c0) = make_float2(v[2], v[3]);
        }
    }
}

// ---------------- fused head-mix + causal softmax (triangle-restricted) ----------------
__global__ void __launch_bounds__(256) softmax_mix_k(
    const float* __restrict__ E, float* __restrict__ sw, const float* __restrict__ qc)
{
    int i = blockIdx.x, b = blockIdx.y;
    int tid = threadIdx.x;
    __shared__ float coef[16][16];
    __shared__ float red[8];
    {
        int h = tid >> 4, g = tid & 15;
        coef[h][g] = ((h==g) ? 1.f : 0.f) + 0.1f * E[h*16 + g];
    }
    __syncthreads();

    int nit = (i >> 8);                 // last active 256-chunk index
    int storeLim = ((i >> 7) + 1) << 7; // cover the k-tile holding row i

    bool valid[4];
#pragma unroll
    for (int it=0; it<4; it++) valid[it] = (tid + 256*it) <= i;

    float acc[16][4];
#pragma unroll
    for (int g=0; g<16; g++){
        const float* row = sw + (((size_t)(b*16+g))*Ss + i)*Ss;
#pragma unroll
        for (int it=0; it<4; it++){
            int j = tid + 256*it;
            acc[g][it] = valid[it] ? row[j] : -1e30f;
        }
    }
    for (int h=0; h<16; h++){
        const float* row = qc + (((size_t)(b*16+h))*Ss + i)*Ss;
        float qv[4];
#pragma unroll
        for (int it=0; it<4; it++){
            int j = tid + 256*it;
            qv[it] = valid[it] ? row[j] : 0.f;
        }
#pragma unroll
        for (int it=0; it<4; it++){
            if (it > nit) break;        // whole chunk masked: skip fma work
#pragma unroll
            for (int g=0; g<16; g++)
                acc[g][it] = fmaf(coef[h][g], qv[it], acc[g][it]);
        }
    }
#pragma unroll
    for (int g=0; g<16; g++){
        float m = -1e30f;
#pragma unroll
        for (int it=0; it<4; it++) if (valid[it]) m = fmaxf(m, acc[g][it]);
        m = blockMax(m, red);
        float e[4], s = 0.f;
#pragma unroll
        for (int it=0; it<4; it++){
            e[it] = valid[it] ? expf(acc[g][it] - m) : 0.f;
            s += e[it];
        }
        s = blockSum(s, red);
        float inv = 1.f / s;
        float* row = sw + (((size_t)(b*16+g))*Ss + i)*Ss;
#pragma unroll
        for (int it=0; it<4; it++){
            int j = tid + 256*it;
            if (j < storeLim) row[j] = e[it] * inv;  // zeros past i within tile
        }
    }
}

// ---------------- fused residual-add + LayerNorm ----------------
__global__ void __launch_bounds__(256) add_ln_k(
    const float* __restrict__ xa, const float* __restrict__ xb,
    const float* __restrict__ gamma, const float* __restrict__ beta,
    float* __restrict__ out)
{
    int r = blockIdx.x;
    int tid = threadIdx.x;
    __shared__ float red[8];
    float v[4], s = 0.f, ss = 0.f;
#pragma unroll
    for (int it=0; it<4; it++){
        int idx = tid + 256*it;
        float a = xa[(size_t)r*Dd + idx] + xb[(size_t)r*Dd + idx];
        v[it] = a; s += a; ss += a*a;
    }
    s  = blockSum(s,  red);
    ss = blockSum(ss, red);
    float mu  = s * (1.f/Dd);
    float var = ss * (1.f/Dd) - mu*mu;
    float rs  = rsqrtf(var + 1e-5f);
#pragma unroll
    for (int it=0; it<4; it++){
        int idx = tid + 256*it;
        out[(size_t)r*Dd + idx] = (v[it] - mu) * rs * gamma[idx] + beta[idx];
    }
}

// ---------------- launch ----------------
extern "C" void kernel_launch(void* const* d_in, const int* in_sizes, int n_in,
                              void* d_out, int out_size)
{
    const float* x   = (const float*)d_in[0];
    const float* Wq  = (const float*)d_in[2];
    const float* bq  = (const float*)d_in[3];
    const float* Wk  = (const float*)d_in[4];
    const float* bk  = (const float*)d_in[5];
    const float* Wv  = (const float*)d_in[6];
    const float* bv  = (const float*)d_in[7];
    const float* Wo  = (const float*)d_in[8];
    const float* bo  = (const float*)d_in[9];
    const float* Wt  = (const float*)d_in[10];
    const float* bt  = (const float*)d_in[11];
    const float* E   = (const float*)d_in[12];
    const float* strengths = (const float*)d_in[13];
    const float* W1  = (const float*)d_in[14];
    const float* b1  = (const float*)d_in[15];
    const float* W2  = (const float*)d_in[16];
    const float* b2  = (const float*)d_in[17];
    const float* thf = (const float*)d_in[18];
    const float* g1  = (const float*)d_in[19];
    const float* be1 = (const float*)d_in[20];
    const float* g3  = (const float*)d_in[21];
    const float* be3 = (const float*)d_in[22];
    float* out = (float*)d_out;

    float *pq,*pk,*pv,*prq,*prk,*psc,*pqc,*pattn,*ptmp,*px1,*phh;
    cudaGetSymbolAddress((void**)&pq,   g_q);
    cudaGetSymbolAddress((void**)&pk,   g_k);
    cudaGetSymbolAddress((void**)&pv,   g_v);
    cudaGetSymbolAddress((void**)&prq,  g_rq);
    cudaGetSymbolAddress((void**)&prk,  g_rk);
    cudaGetSymbolAddress((void**)&psc,  g_sc);
    cudaGetSymbolAddress((void**)&pqc,  g_qc);
    cudaGetSymbolAddress((void**)&pattn,g_attn);
    cudaGetSymbolAddress((void**)&ptmp, g_tmp);
    cudaGetSymbolAddress((void**)&px1,  g_x1);
    cudaGetSymbolAddress((void**)&phh,  g_hh);

    dim3 blk(256);
    const long SD = (long)Ss*Dd, SS = (long)Ss*Ss;
    // QKV projections
    gemm_k<0,0,0,0><<<dim3(16,32,1), blk>>>(x, Wq, bq, pq, Mrows,Dd,Dd, Dd,Dd,Dd, 0,0,0,0,0,0,1, nullptr, 1.f);
    gemm_k<0,0,0,0><<<dim3(16,32,1), blk>>>(x, Wk, bk, pk, Mrows,Dd,Dd, Dd,Dd,Dd, 0,0,0,0,0,0,1, nullptr, 1.f);
    gemm_k<0,0,0,0><<<dim3(16,32,1), blk>>>(x, Wv, bv, pv, Mrows,Dd,Dd, Dd,Dd,Dd, 0,0,0,0,0,0,1, nullptr, 1.f);
    // theta projection + r = cos(pi*sigmoid)
    gemm_k<0,2,0,0><<<dim3(1,512,1), blk>>>(pq, Wt, bt, prq, Mrows*Hh,DKk,DKk, DKk,DKk,DKk, 0,0,0,0,0,0,1, nullptr, 1.f);
    gemm_k<0,2,0,0><<<dim3(1,512,1), blk>>>(pk, Wt, bt, prk, Mrows*Hh,DKk,DKk, DKk,DKk,DKk, 0,0,0,0,0,0,1, nullptr, 1.f);
    // scores = q k^T / 8  (tensor-core, causal-skipped), per (b,h)
    gemm_k<0,3,1,0><<<dim3(16,8,Bb*Hh), blk>>>(pq, pk, nullptr, psc,
        Ss, Ss, DKk, Dd, Dd, Ss,
        SD, (long)DKk, SD, (long)DKk, (long)Hh*SS, SS, Hh, nullptr, 0.125f);
    // qc = rq rk^T * strengths[h]
    gemm_k<0,3,1,0><<<dim3(16,8,Bb*Hh), blk>>>(prq, prk, nullptr, pqc,
        Ss, Ss, DKk, Dd, Dd, Ss,
        SD, (long)DKk, SD, (long)DKk, (long)Hh*SS, SS, Hh, strengths, 1.f);
    // head-mix + softmax (in place on scores buffer, triangle-restricted)
    softmax_mix_k<<<dim3(Ss,Bb), blk>>>(E, psc, pqc);
    // attn = w @ v  (k-loop truncated to causal extent)
    gemm_k<1,0,0,1><<<dim3(1,8,Bb*Hh), blk>>>(psc, pv, nullptr, pattn,
        Ss, DKk, Ss, Ss, Dd, Dd,
        (long)Hh*SS, SS, SD, (long)DKk, SD, (long)DKk, Hh, nullptr, 1.f);
    // output projection
    gemm_k<0,0,0,0><<<dim3(16,32,1), blk>>>(pattn, Wo, bo, ptmp, Mrows,Dd,Dd, Dd,Dd,Dd, 0,0,0,0,0,0,1, nullptr, 1.f);
    // x1 = LN(x + attn_out)
    add_ln_k<<<Mrows, blk>>>(x, ptmp, g1, be1, px1);
    // FFN up (exact GELU * quantum gate fused in epilogue)
    gemm_k<0,1,0,0><<<dim3(64,32,1), blk>>>(px1, W1, b1, phh, Mrows,DFFf,Dd, Dd,Dd,DFFf, 0,0,0,0,0,0,1, thf, 1.f);
    // FFN down
    gemm_k<0,0,0,0><<<dim3(16,32,1), blk>>>(phh, W2, b2, ptmp, Mrows,Dd,DFFf, DFFf,DFFf,Dd, 0,0,0,0,0,0,1, nullptr, 1.f);
    // out = LN(x1 + ff)
    add_ln_k<<<Mrows, blk>>>(px1, ptmp, g3, be3, out);
    (void)in_sizes; (void)n_in; (void)out_size;
}

// round 12
// speedup vs baseline: 2.3783x; 1.0129x over previous
#include <cuda_runtime.h>
#include <cuda_bf16.h>
#include <cstdint>
#include <cstddef>

#define Bb   4
#define Ss   1024
#define Dd   1024
#define Hh   16
#define DKk  64
#define DFFf 4096
#define Mrows (Bb*Ss)

typedef __nv_bfloat16 bf16;

// ---------------- scratch (device globals; no allocation) ----------------
__device__ float g_sc [(size_t)Bb*Hh*Ss*Ss];
__device__ float g_qc [(size_t)Bb*Hh*Ss*Ss];
__device__ float g_tmp[(size_t)Mrows*Dd];
__device__ float g_x1 [(size_t)Mrows*Dd];

__device__ bf16 g_xh [(size_t)Mrows*Dd],  g_xl [(size_t)Mrows*Dd];
__device__ bf16 g_qh [(size_t)Mrows*Dd],  g_ql [(size_t)Mrows*Dd];
__device__ bf16 g_kh [(size_t)Mrows*Dd],  g_kl [(size_t)Mrows*Dd];
__device__ bf16 g_vh [(size_t)Mrows*Dd],  g_vl [(size_t)Mrows*Dd];
__device__ bf16 g_rqh[(size_t)Mrows*Dd],  g_rql[(size_t)Mrows*Dd];
__device__ bf16 g_rkh[(size_t)Mrows*Dd],  g_rkl[(size_t)Mrows*Dd];
__device__ bf16 g_ath[(size_t)Mrows*Dd],  g_atl[(size_t)Mrows*Dd];
__device__ bf16 g_x1h[(size_t)Mrows*Dd],  g_x1l[(size_t)Mrows*Dd];
__device__ bf16 g_hhh[(size_t)Mrows*DFFf],g_hhl[(size_t)Mrows*DFFf];
__device__ bf16 g_wh [(size_t)Bb*Hh*Ss*Ss], g_wl [(size_t)Bb*Hh*Ss*Ss];
__device__ bf16 g_Wqh[(size_t)Dd*Dd],  g_Wql[(size_t)Dd*Dd];
__device__ bf16 g_Wkh[(size_t)Dd*Dd],  g_Wkl[(size_t)Dd*Dd];
__device__ bf16 g_Wvh[(size_t)Dd*Dd],  g_Wvl[(size_t)Dd*Dd];
__device__ bf16 g_Woh[(size_t)Dd*Dd],  g_Wol[(size_t)Dd*Dd];
__device__ bf16 g_Wth[(size_t)DKk*DKk],g_Wtl[(size_t)DKk*DKk];
__device__ bf16 g_W1h[(size_t)DFFf*Dd],g_W1l[(size_t)DFFf*Dd];
__device__ bf16 g_W2h[(size_t)Dd*DFFf],g_W2l[(size_t)Dd*DFFf];

// ---------------- reductions ----------------
__device__ __forceinline__ float warpSum(float v){
#pragma unroll
    for (int o=16;o;o>>=1) v += __shfl_xor_sync(0xffffffffu, v, o);
    return v;
}
__device__ __forceinline__ float warpMax(float v){
#pragma unroll
    for (int o=16;o;o>>=1) v = fmaxf(v, __shfl_xor_sync(0xffffffffu, v, o));
    return v;
}
__device__ __forceinline__ float blockSum(float v, float* red){
    int lane = threadIdx.x & 31, w = threadIdx.x >> 5;
    v = warpSum(v);
    __syncthreads();
    if (lane == 0) red[w] = v;
    __syncthreads();
    float r = red[0];
#pragma unroll
    for (int i=1;i<8;i++) r += red[i];
    return r;
}
__device__ __forceinline__ float blockMax(float v, float* red){
    int lane = threadIdx.x & 31, w = threadIdx.x >> 5;
    v = warpMax(v);
    __syncthreads();
    if (lane == 0) red[w] = v;
    __syncthreads();
    float r = red[0];
#pragma unroll
    for (int i=1;i<8;i++) r = fmaxf(r, red[i]);
    return r;
}

// ---------------- helpers ----------------
__device__ __forceinline__ void ldsm4(uint32_t* r, uint32_t addr){
    asm volatile("ldmatrix.sync.aligned.m8n8.x4.shared.b16 {%0,%1,%2,%3},[%4];"
        : "=r"(r[0]),"=r"(r[1]),"=r"(r[2]),"=r"(r[3]) : "r"(addr));
}
__device__ __forceinline__ void ldsm4t(uint32_t* r, uint32_t addr){
    asm volatile("ldmatrix.sync.aligned.m8n8.x4.trans.shared.b16 {%0,%1,%2,%3},[%4];"
        : "=r"(r[0]),"=r"(r[1]),"=r"(r[2]),"=r"(r[3]) : "r"(addr));
}
__device__ __forceinline__ void mma16816(float* d, const uint32_t* a, uint32_t b0, uint32_t b1){
    asm volatile("mma.sync.aligned.m16n8k16.row.col.f32.bf16.bf16.f32 "
        "{%0,%1,%2,%3},{%4,%5,%6,%7},{%8,%9},{%0,%1,%2,%3};"
        : "+f"(d[0]),"+f"(d[1]),"+f"(d[2]),"+f"(d[3])
        : "r"(a[0]),"r"(a[1]),"r"(a[2]),"r"(a[3]),"r"(b0),"r"(b1));
}
__device__ __forceinline__ void cpa16(uint32_t saddr, const bf16* g){
    uint64_t ga = __cvta_generic_to_global((const void*)g);
    asm volatile("cp.async.cg.shared.global [%0], [%1], 16;" :: "r"(saddr), "l"(ga));
}
__device__ __forceinline__ uint32_t pack2(bf16 a, bf16 b){
    return (uint32_t)__bfloat16_as_ushort(a) | ((uint32_t)__bfloat16_as_ushort(b) << 16);
}
__device__ __forceinline__ void split4(float4 v, uint2& hi, uint2& lo){
    bf16 h0=__float2bfloat16(v.x), h1=__float2bfloat16(v.y);
    bf16 h2=__float2bfloat16(v.z), h3=__float2bfloat16(v.w);
    bf16 l0=__float2bfloat16(v.x-__bfloat162float(h0));
    bf16 l1=__float2bfloat16(v.y-__bfloat162float(h1));
    bf16 l2=__float2bfloat16(v.z-__bfloat162float(h2));
    bf16 l3=__float2bfloat16(v.w-__bfloat162float(h3));
    hi.x = pack2(h0,h1); hi.y = pack2(h2,h3);
    lo.x = pack2(l0,l1); lo.y = pack2(l2,l3);
}

// ---------------- elementwise fp32 -> bf16 hi/lo split ----------------
__global__ void __launch_bounds__(256) split_k(
    const float* __restrict__ src, bf16* __restrict__ hi, bf16* __restrict__ lo, int n4)
{
    int i = blockIdx.x*256 + threadIdx.x;
    if (i >= n4) return;
    float4 v = ((const float4*)src)[i];
    uint2 h, l; split4(v, h, l);
    ((uint2*)hi)[i] = h;
    ((uint2*)lo)[i] = l;
}

// ---------------- tensor-core GEMM on pre-split bf16 hi/lo operands ----------------
// C = (Ah+Al) @ (Bh+Bl)(^T) + bias   (3-pass split: AhBh + AhBl + AlBh, fp32 acc)
// BMODE 0: B is [N,K] row-major (ldb=K-ish)   BMODE 1: B is [K,N] row-major
// EPI 0 none; 1 GELU*(1+0.1|sin2th|); 2 cos(pi*sigmoid); 3 scale
// CAUSAL: skip tiles n0>m0+127.  TRIK: k stops at m0+128.
// OUT 0: fp32 C.  OUT 1: bf16 hi/lo pair Ch/Cl.
// Tiles: BM=128,BN=64,BK=32; 256 thr; double-buffered cp.async smem.
template<int BMODE,int EPI,int CAUSAL,int TRIK,int OUT>
__global__ void __launch_bounds__(256) gemm_bf(
    const bf16* __restrict__ Ah, const bf16* __restrict__ Al,
    const bf16* __restrict__ Bh, const bf16* __restrict__ Bl,
    const float* __restrict__ bias,
    float* __restrict__ C, bf16* __restrict__ Ch, bf16* __restrict__ Cl,
    int M, int N, int K, int lda, int ldb, int ldc,
    long sA, long sA2, long sB, long sB2, long sC, long sC2, int Hdim,
    const float* __restrict__ extra, float cscale)
{
    const int BKP = 40;   // A/B0 tile row stride (elts)
    const int BNP = 72;   // B1 tile row stride

    int n0 = blockIdx.x * 64;
    int m0 = blockIdx.y * 128;
    if (CAUSAL && n0 > m0 + 127) return;

    int z = blockIdx.z;
    int zh = (Hdim > 1) ? (z % Hdim) : 0;
    long aoff, boff, coff;
    if (Hdim > 1) {
        int zb = z / Hdim;
        aoff = (long)zb*sA + (long)zh*sA2;
        boff = (long)zb*sB + (long)zh*sB2;
        coff = (long)zb*sC + (long)zh*sC2;
    } else {
        aoff = (long)z*sA; boff = (long)z*sB; coff = (long)z*sC;
    }
    const bf16* Azh = Ah + aoff; const bf16* Azl = Al + aoff;
    const bf16* Bzh = Bh + boff; const bf16* Bzl = Bl + boff;

    int Keff = K;
    if (TRIK) { Keff = m0 + 128; if (Keff > K) Keff = K; }

    int tid = threadIdx.x;
    int lane = tid & 31;
    int w = tid >> 5;
    int wm = w & 3;
    int wn = w >> 2;

    // dynamic smem: AH[2][5120], AL[2][5120], BH[2][2560], BL[2][2560] (elts)
    extern __shared__ __align__(16) bf16 smem[];
    uint32_t sAH = (uint32_t)__cvta_generic_to_shared(smem);
    uint32_t sAL = sAH + 10240*2;
    uint32_t sBH = sAH + 20480*2;
    uint32_t sBL = sAH + 25600*2;

    float acc[2][4][4];
#pragma unroll
    for (int i=0;i<2;i++)
#pragma unroll
        for (int j=0;j<4;j++)
#pragma unroll
            for (int q=0;q<4;q++) acc[i][j][q] = 0.f;

    // ldmatrix coords
    int a_r = wm*32 + (lane & 7) + ((lane >> 3) & 1) * 8;
    int a_c = (lane >> 4) * 8;
    int b0_r = wn*32 + (lane & 7) + ((lane >= 16) ? 8 : 0);
    int b0_c = ((lane >> 3) & 1) * 8;
    int b1_r = (lane & 7) + ((lane >> 3) & 1) * 8;
    int b1_c = wn*32 + ((lane >= 16) ? 8 : 0);

    // cp.async coords
    int rowA = tid >> 2;           // 0..63
    int chA  = (tid & 3) * 8;
    int rowB1 = tid >> 3;          // 0..31 (BMODE1)
    int chB1  = (tid & 7) * 8;

#define LOAD_STAGE(s, kk) do {                                                   \
    uint32_t ao = (uint32_t)(s)*5120*2;                                          \
    uint32_t bo = (uint32_t)(s)*2560*2;                                          \
    _Pragma("unroll")                                                            \
    for (int r=0;r<2;r++){                                                       \
        int row = r*64 + rowA;                                                   \
        size_t go = (size_t)(m0+row)*lda + (kk) + chA;                           \
        uint32_t d = ao + (uint32_t)(row*BKP + chA)*2;                           \
        cpa16(sAH + d, Azh + go);                                                \
        cpa16(sAL + d, Azl + go);                                                \
    }                                                                            \
    if (BMODE == 0){                                                             \
        size_t go = (size_t)(n0+rowA)*ldb + (kk) + chA;                          \
        uint32_t d = bo + (uint32_t)(rowA*BKP + chA)*2;                          \
        cpa16(sBH + d, Bzh + go);                                                \
        cpa16(sBL + d, Bzl + go);                                                \
    } else {                                                                     \
        size_t go = (size_t)((kk)+rowB1)*ldb + n0 + chB1;                        \
        uint32_t d = bo + (uint32_t)(rowB1*BNP + chB1)*2;                        \
        cpa16(sBH + d, Bzh + go);                                                \
        cpa16(sBL + d, Bzl + go);                                                \
    }                                                                            \
    asm volatile("cp.async.commit_group;");                                      \
} while(0)

    LOAD_STAGE(0, 0);

    int s = 0;
    for (int k0 = 0;;) {
        int kn = k0 + 32;
        bool more = kn < Keff;
        if (more) LOAD_STAGE(s^1, kn);
        if (more) { asm volatile("cp.async.wait_group 1;"); }
        else      { asm volatile("cp.async.wait_group 0;"); }
        __syncthreads();

        uint32_t ao = (uint32_t)s*5120*2;
        uint32_t bo = (uint32_t)s*2560*2;
#pragma unroll
        for (int ks=0; ks<2; ks++){
            uint32_t ah[2][4], al[2][4], bh[2][4], bl[2][4];
#pragma unroll
            for (int mi=0; mi<2; mi++){
                uint32_t off = ao + (uint32_t)((a_r + mi*16)*BKP + a_c + ks*16) * 2;
                ldsm4(ah[mi], sAH + off);
                ldsm4(al[mi], sAL + off);
            }
            if (BMODE == 0){
#pragma unroll
                for (int nt=0; nt<2; nt++){
                    uint32_t off = bo + (uint32_t)((b0_r + nt*16)*BKP + b0_c + ks*16) * 2;
                    ldsm4(bh[nt], sBH + off);
                    ldsm4(bl[nt], sBL + off);
                }
            } else {
#pragma unroll
                for (int nt=0; nt<2; nt++){
                    uint32_t off = bo + (uint32_t)((b1_r + ks*16)*BNP + b1_c + nt*16) * 2;
                    ldsm4t(bh[nt], sBH + off);
                    ldsm4t(bl[nt], sBL + off);
                }
            }
#pragma unroll
            for (int mi=0; mi<2; mi++)
#pragma unroll
                for (int ni=0; ni<4; ni++){
                    const uint32_t* bq = &bh[ni>>1][(ni&1)*2];
                    mma16816(acc[mi][ni], ah[mi], bq[0], bq[1]);
                }
#pragma unroll
            for (int mi=0; mi<2; mi++)
#pragma unroll
                for (int ni=0; ni<4; ni++){
                    const uint32_t* bq = &bl[ni>>1][(ni&1)*2];
                    mma16816(acc[mi][ni], ah[mi], bq[0], bq[1]);
                }
#pragma unroll
            for (int mi=0; mi<2; mi++)
#pragma unroll
                for (int ni=0; ni<4; ni++){
                    const uint32_t* bq = &bh[ni>>1][(ni&1)*2];
                    mma16816(acc[mi][ni], al[mi], bq[0], bq[1]);
                }
        }

        if (!more) break;
        __syncthreads();   // all warps done reading stage s before next overwrite
        s ^= 1; k0 = kn;
    }
#undef LOAD_STAGE

    // ---- epilogue ----
    float scal = 1.f;
    if (EPI == 3) scal = cscale * (extra ? extra[zh] : 1.f);
    int g = lane >> 2, t2 = (lane & 3) * 2;
#pragma unroll
    for (int mi=0; mi<2; mi++){
        int r0 = m0 + wm*32 + mi*16 + g;
#pragma unroll
        for (int ni=0; ni<4; ni++){
            int c0 = n0 + wn*32 + ni*8 + t2;
            float b0v = bias ? bias[c0]   : 0.f;
            float b1v = bias ? bias[c0+1] : 0.f;
            float v[4];
            v[0] = acc[mi][ni][0] + b0v;
            v[1] = acc[mi][ni][1] + b1v;
            v[2] = acc[mi][ni][2] + b0v;
            v[3] = acc[mi][ni][3] + b1v;
            if (EPI == 1){
                float th0 = extra[c0], th1 = extra[c0+1];
                float q0 = 1.f + 0.1f * fabsf(sinf(2.f*th0));
                float q1 = 1.f + 0.1f * fabsf(sinf(2.f*th1));
#pragma unroll
                for (int q=0;q<4;q++){
                    float ge = 0.5f * v[q] * (1.f + erff(v[q] * 0.70710678118654752f));
                    v[q] = ge * ((q&1) ? q1 : q0);
                }
            } else if (EPI == 2){
#pragma unroll
                for (int q=0;q<4;q++){
                    float sg = 1.f / (1.f + expf(-v[q]));
                    v[q] = cospif(sg);
                }
            } else if (EPI == 3){
#pragma unroll
                for (int q=0;q<4;q++) v[q] *= scal;
            }
            if (OUT == 0){
                float* Cz = C + coff;
                *(float2*)(Cz + (size_t)r0*ldc + c0)     = make_float2(v[0], v[1]);
                *(float2*)(Cz + (size_t)(r0+8)*ldc + c0) = make_float2(v[2], v[3]);
            } else {
                bf16* Chz = Ch + coff;
                bf16* Clz = Cl + coff;
#pragma unroll
                for (int rr=0; rr<2; rr++){
                    float x0 = v[rr*2], x1v = v[rr*2+1];
                    bf16 h0 = __float2bfloat16(x0), h1 = __float2bfloat16(x1v);
                    bf16 l0 = __float2bfloat16(x0 - __bfloat162float(h0));
                    bf16 l1 = __float2bfloat16(x1v - __bfloat162float(h1));
                    size_t o = (size_t)(r0 + rr*8)*ldc + c0;
                    *(uint32_t*)(Chz + o) = pack2(h0, h1);
                    *(uint32_t*)(Clz + o) = pack2(l0, l1);
                }
            }
        }
    }
}

// ---------------- fused head-mix + causal softmax (writes bf16 hi/lo) ----------------
__global__ void __launch_bounds__(256) softmax_mix_k(
    const float* __restrict__ E, const float* __restrict__ sc, const float* __restrict__ qc,
    bf16* __restrict__ wh, bf16* __restrict__ wl)
{
    int i = blockIdx.x, b = blockIdx.y;
    int tid = threadIdx.x;
    __shared__ float coef[16][16];
    __shared__ float red[8];
    {
        int h = tid >> 4, g = tid & 15;
        coef[h][g] = ((h==g) ? 1.f : 0.f) + 0.1f * E[h*16 + g];
    }
    __syncthreads();

    int nit = (i >> 8);
    int storeLim = ((i >> 7) + 1) << 7;

    bool valid[4];
#pragma unroll
    for (int it=0; it<4; it++) valid[it] = (tid + 256*it) <= i;

    float acc[16][4];
#pragma unroll
    for (int g=0; g<16; g++){
        const float* row = sc + (((size_t)(b*16+g))*Ss + i)*Ss;
#pragma unroll
        for (int it=0; it<4; it++){
            int j = tid + 256*it;
            acc[g][it] = valid[it] ? row[j] : -1e30f;
        }
    }
    for (int h=0; h<16; h++){
        const float* row = qc + (((size_t)(b*16+h))*Ss + i)*Ss;
        float qv[4];
#pragma unroll
        for (int it=0; it<4; it++){
            int j = tid + 256*it;
            qv[it] = valid[it] ? row[j] : 0.f;
        }
#pragma unroll
        for (int it=0; it<4; it++){
            if (it > nit) break;
#pragma unroll
            for (int g=0; g<16; g++)
                acc[g][it] = fmaf(coef[h][g], qv[it], acc[g][it]);
        }
    }
#pragma unroll
    for (int g=0; g<16; g++){
        float m = -1e30f;
#pragma unroll
        for (int it=0; it<4; it++) if (valid[it]) m = fmaxf(m, acc[g][it]);
        m = blockMax(m, red);
        float e[4], s = 0.f;
#pragma unroll
        for (int it=0; it<4; it++){
            e[it] = valid[it] ? expf(acc[g][it] - m) : 0.f;
            s += e[it];
        }
        s = blockSum(s, red);
        float inv = 1.f / s;
        size_t ro = (((size_t)(b*16+g))*Ss + i)*Ss;
#pragma unroll
        for (int it=0; it<4; it++){
            int j = tid + 256*it;
            if (j < storeLim){
                float wv = e[it] * inv;
                bf16 h = __float2bfloat16(wv);
                wh[ro + j] = h;
                wl[ro + j] = __float2bfloat16(wv - __bfloat162float(h));
            }
        }
    }
}

// ---------------- fused residual-add + LayerNorm (optional bf16 hi/lo out) ----------------
template<int WRITEBF>
__global__ void __launch_bounds__(256) add_ln_k(
    const float* __restrict__ xa, const float* __restrict__ xb,
    const float* __restrict__ gamma, const float* __restrict__ beta,
    float* __restrict__ out, bf16* __restrict__ oh, bf16* __restrict__ ol)
{
    int r = blockIdx.x;
    int tid = threadIdx.x;
    __shared__ float red[8];
    float v[4], s = 0.f, ss = 0.f;
#pragma unroll
    for (int it=0; it<4; it++){
        int idx = tid + 256*it;
        float a = xa[(size_t)r*Dd + idx] + xb[(size_t)r*Dd + idx];
        v[it] = a; s += a; ss += a*a;
    }
    s  = blockSum(s,  red);
    ss = blockSum(ss, red);
    float mu  = s * (1.f/Dd);
    float var = ss * (1.f/Dd) - mu*mu;
    float rs  = rsqrtf(var + 1e-5f);
#pragma unroll
    for (int it=0; it<4; it++){
        int idx = tid + 256*it;
        float o = (v[it] - mu) * rs * gamma[idx] + beta[idx];
        out[(size_t)r*Dd + idx] = o;
        if (WRITEBF){
            bf16 h = __float2bfloat16(o);
            oh[(size_t)r*Dd + idx] = h;
            ol[(size_t)r*Dd + idx] = __float2bfloat16(o - __bfloat162float(h));
        }
    }
}

// ---------------- launch ----------------
#define SMEM_BYTES 61440

extern "C" void kernel_launch(void* const* d_in, const int* in_sizes, int n_in,
                              void* d_out, int out_size)
{
    const float* x   = (const float*)d_in[0];
    const float* Wq  = (const float*)d_in[2];
    const float* bq  = (const float*)d_in[3];
    const float* Wk  = (const float*)d_in[4];
    const float* bk  = (const float*)d_in[5];
    const float* Wv  = (const float*)d_in[6];
    const float* bv  = (const float*)d_in[7];
    const float* Wo  = (const float*)d_in[8];
    const float* bo  = (const float*)d_in[9];
    const float* Wt  = (const float*)d_in[10];
    const float* bt  = (const float*)d_in[11];
    const float* E   = (const float*)d_in[12];
    const float* strengths = (const float*)d_in[13];
    const float* W1  = (const float*)d_in[14];
    const float* b1  = (const float*)d_in[15];
    const float* W2  = (const float*)d_in[16];
    const float* b2  = (const float*)d_in[17];
    const float* thf = (const float*)d_in[18];
    const float* g1  = (const float*)d_in[19];
    const float* be1 = (const float*)d_in[20];
    const float* g3  = (const float*)d_in[21];
    const float* be3 = (const float*)d_in[22];
    float* out = (float*)d_out;

    float *psc,*pqc,*ptmp,*px1;
    cudaGetSymbolAddress((void**)&psc,  g_sc);
    cudaGetSymbolAddress((void**)&pqc,  g_qc);
    cudaGetSymbolAddress((void**)&ptmp, g_tmp);
    cudaGetSymbolAddress((void**)&px1,  g_x1);
    bf16 *xh,*xl,*qh,*ql,*kh,*kl,*vh,*vl,*rqh,*rql,*rkh,*rkl,*ath,*atl,*x1h,*x1l,*hhh,*hhl,*wh,*wl;
    bf16 *Wqh,*Wql,*Wkh,*Wkl,*Wvh,*Wvl,*Woh,*Wol,*Wth,*Wtl,*W1h,*W1l,*W2h,*W2l;
    cudaGetSymbolAddress((void**)&xh, g_xh);  cudaGetSymbolAddress((void**)&xl, g_xl);
    cudaGetSymbolAddress((void**)&qh, g_qh);  cudaGetSymbolAddress((void**)&ql, g_ql);
    cudaGetSymbolAddress((void**)&kh, g_kh);  cudaGetSymbolAddress((void**)&kl, g_kl);
    cudaGetSymbolAddress((void**)&vh, g_vh);  cudaGetSymbolAddress((void**)&vl, g_vl);
    cudaGetSymbolAddress((void**)&rqh,g_rqh); cudaGetSymbolAddress((void**)&rql,g_rql);
    cudaGetSymbolAddress((void**)&rkh,g_rkh); cudaGetSymbolAddress((void**)&rkl,g_rkl);
    cudaGetSymbolAddress((void**)&ath,g_ath); cudaGetSymbolAddress((void**)&atl,g_atl);
    cudaGetSymbolAddress((void**)&x1h,g_x1h); cudaGetSymbolAddress((void**)&x1l,g_x1l);
    cudaGetSymbolAddress((void**)&hhh,g_hhh); cudaGetSymbolAddress((void**)&hhl,g_hhl);
    cudaGetSymbolAddress((void**)&wh, g_wh);  cudaGetSymbolAddress((void**)&wl, g_wl);
    cudaGetSymbolAddress((void**)&Wqh,g_Wqh); cudaGetSymbolAddress((void**)&Wql,g_Wql);
    cudaGetSymbolAddress((void**)&Wkh,g_Wkh); cudaGetSymbolAddress((void**)&Wkl,g_Wkl);
    cudaGetSymbolAddress((void**)&Wvh,g_Wvh); cudaGetSymbolAddress((void**)&Wvl,g_Wvl);
    cudaGetSymbolAddress((void**)&Woh,g_Woh); cudaGetSymbolAddress((void**)&Wol,g_Wol);
    cudaGetSymbolAddress((void**)&Wth,g_Wth); cudaGetSymbolAddress((void**)&Wtl,g_Wtl);
    cudaGetSymbolAddress((void**)&W1h,g_W1h); cudaGetSymbolAddress((void**)&W1l,g_W1l);
    cudaGetSymbolAddress((void**)&W2h,g_W2h); cudaGetSymbolAddress((void**)&W2l,g_W2l);

    // raise dynamic smem limit for all instantiations (idempotent, capture-safe)
    cudaFuncSetAttribute(gemm_bf<0,0,0,0,1>, cudaFuncAttributeMaxDynamicSharedMemorySize, SMEM_BYTES);
    cudaFuncSetAttribute(gemm_bf<0,2,0,0,1>, cudaFuncAttributeMaxDynamicSharedMemorySize, SMEM_BYTES);
    cudaFuncSetAttribute(gemm_bf<0,3,1,0,0>, cudaFuncAttributeMaxDynamicSharedMemorySize, SMEM_BYTES);
    cudaFuncSetAttribute(gemm_bf<1,0,0,1,1>, cudaFuncAttributeMaxDynamicSharedMemorySize, SMEM_BYTES);
    cudaFuncSetAttribute(gemm_bf<0,0,0,0,0>, cudaFuncAttributeMaxDynamicSharedMemorySize, SMEM_BYTES);
    cudaFuncSetAttribute(gemm_bf<0,1,0,0,1>, cudaFuncAttributeMaxDynamicSharedMemorySize, SMEM_BYTES);

    dim3 blk(256);
    const long SD = (long)Ss*Dd, SS = (long)Ss*Ss;

    // split inputs & weights to bf16 hi/lo (once per call; cheap)
    split_k<<<(Mrows*Dd/4+255)/256, blk>>>(x,  xh,  xl,  Mrows*Dd/4);
    split_k<<<(Dd*Dd/4+255)/256,   blk>>>(Wq, Wqh, Wql, Dd*Dd/4);
    split_k<<<(Dd*Dd/4+255)/256,   blk>>>(Wk, Wkh, Wkl, Dd*Dd/4);
    split_k<<<(Dd*Dd/4+255)/256,   blk>>>(Wv, Wvh, Wvl, Dd*Dd/4);
    split_k<<<(Dd*Dd/4+255)/256,   blk>>>(Wo, Woh, Wol, Dd*Dd/4);
    split_k<<<(DKk*DKk/4+255)/256, blk>>>(Wt, Wth, Wtl, DKk*DKk/4);
    split_k<<<(DFFf*Dd/4+255)/256, blk>>>(W1, W1h, W1l, DFFf*Dd/4);
    split_k<<<(Dd*DFFf/4+255)/256, blk>>>(W2, W2h, W2l, Dd*DFFf/4);

    // QKV projections -> bf16 hi/lo
    gemm_bf<0,0,0,0,1><<<dim3(16,32,1), blk, SMEM_BYTES>>>(xh,xl, Wqh,Wql, bq, nullptr,qh,ql,
        Mrows,Dd,Dd, Dd,Dd,Dd, 0,0,0,0,0,0,1, nullptr, 1.f);
    gemm_bf<0,0,0,0,1><<<dim3(16,32,1), blk, SMEM_BYTES>>>(xh,xl, Wkh,Wkl, bk, nullptr,kh,kl,
        Mrows,Dd,Dd, Dd,Dd,Dd, 0,0,0,0,0,0,1, nullptr, 1.f);
    gemm_bf<0,0,0,0,1><<<dim3(16,32,1), blk, SMEM_BYTES>>>(xh,xl, Wvh,Wvl, bv, nullptr,vh,vl,
        Mrows,Dd,Dd, Dd,Dd,Dd, 0,0,0,0,0,0,1, nullptr, 1.f);
    // theta projection + r = cos(pi*sigmoid) -> bf16 hi/lo
    gemm_bf<0,2,0,0,1><<<dim3(1,512,1), blk, SMEM_BYTES>>>(qh,ql, Wth,Wtl, bt, nullptr,rqh,rql,
        Mrows*Hh,DKk,DKk, DKk,DKk,DKk, 0,0,0,0,0,0,1, nullptr, 1.f);
    gemm_bf<0,2,0,0,1><<<dim3(1,512,1), blk, SMEM_BYTES>>>(kh,kl, Wth,Wtl, bt, nullptr,rkh,rkl,
        Mrows*Hh,DKk,DKk, DKk,DKk,DKk, 0,0,0,0,0,0,1, nullptr, 1.f);
    // scores = q k^T / 8 (causal-skipped, per (b,h)) -> fp32
    gemm_bf<0,3,1,0,0><<<dim3(16,8,Bb*Hh), blk, SMEM_BYTES>>>(qh,ql, kh,kl, nullptr, psc,nullptr,nullptr,
        Ss, Ss, DKk, Dd, Dd, Ss,
        SD, (long)DKk, SD, (long)DKk, (long)Hh*SS, SS, Hh, nullptr, 0.125f);
    // qc = rq rk^T * strengths[h]
    gemm_bf<0,3,1,0,0><<<dim3(16,8,Bb*Hh), blk, SMEM_BYTES>>>(rqh,rql, rkh,rkl, nullptr, pqc,nullptr,nullptr,
        Ss, Ss, DKk, Dd, Dd, Ss,
        SD, (long)DKk, SD, (long)DKk, (long)Hh*SS, SS, Hh, strengths, 1.f);
    // head-mix + softmax -> w bf16 hi/lo
    softmax_mix_k<<<dim3(Ss,Bb), blk>>>(E, psc, pqc, wh, wl);
    // attn = w @ v (k truncated to causal extent) -> bf16 hi/lo
    gemm_bf<1,0,0,1,1><<<dim3(1,8,Bb*Hh), blk, SMEM_BYTES>>>(wh,wl, vh,vl, nullptr, nullptr,ath,atl,
        Ss, DKk, Ss, Ss, Dd, Dd,
        (long)Hh*SS, SS, SD, (long)DKk, SD, (long)DKk, Hh, nullptr, 1.f);
    // output projection -> fp32
    gemm_bf<0,0,0,0,0><<<dim3(16,32,1), blk, SMEM_BYTES>>>(ath,atl, Woh,Wol, bo, ptmp,nullptr,nullptr,
        Mrows,Dd,Dd, Dd,Dd,Dd, 0,0,0,0,0,0,1, nullptr, 1.f);
    // x1 = LN(x + attn_out), also bf16 hi/lo
    add_ln_k<1><<<Mrows, blk>>>(x, ptmp, g1, be1, px1, x1h, x1l);
    // FFN up (GELU * quantum gate fused) -> bf16 hi/lo
    gemm_bf<0,1,0,0,1><<<dim3(64,32,1), blk, SMEM_BYTES>>>(x1h,x1l, W1h,W1l, b1, nullptr,hhh,hhl,
        Mrows,DFFf,Dd, Dd,Dd,DFFf, 0,0,0,0,0,0,1, thf, 1.f);
    // FFN down -> fp32
    gemm_bf<0,0,0,0,0><<<dim3(16,32,1), blk, SMEM_BYTES>>>(hhh,hhl, W2h,W2l, b2, ptmp,nullptr,nullptr,
        Mrows,Dd,DFFf, DFFf,DFFf,Dd, 0,0,0,0,0,0,1, nullptr, 1.f);
    // out = LN(x1 + ff)
    add_ln_k<0><<<Mrows, blk>>>(px1, ptmp, g3, be3, out, nullptr, nullptr);
    (void)in_sizes; (void)n_in; (void)out_size;
}